// round 1
// baseline (speedup 1.0000x reference)
#include <cuda_runtime.h>
#include <math.h>

// ---------------- problem dimensions ----------------
#define BSZ   8192
#define D0    1024
#define D1    768
#define DIB   1024
#define KTOT  2816      // D0 + D1 + DIB
#define DOUT  1536
#define R1N   512
#define R2N   100
#define R2P   128       // padded
#define NEXP  7
#define BN_EPS 1e-5f

// ---------------- scratch (device globals; no allocation allowed) -----------
__device__ float g_Wavg[KTOT * DOUT];        // averaged, concatenated weights [2816][1536]
__device__ float g_bavg[3 * DOUT];           // averaged biases per segment
__device__ float g_H1[BSZ * R1N];            // router hidden 1 (in-place BN+relu)
__device__ float g_H2[BSZ * R2P];            // router hidden 2 (padded to 128)
__device__ float g_rw2p[R1N * R2P];          // padded rw2
__device__ float g_rb2p[R2P];
__device__ float g_s1[R1N], g_q1[R1N];       // col sum / sumsq for BN1
__device__ float g_s2[R2P], g_q2[R2P];       // col sum / sumsq for BN2
__device__ float g_w[BSZ * 3];               // router weights
__device__ float g_Xs[BSZ * KTOT];           // router-scaled concatenated inputs

// ---------------- kernels ----------------

__global__ void zero_stats_kernel() {
    int i = threadIdx.x + blockIdx.x * blockDim.x;
    if (i < R1N) { g_s1[i] = 0.f; g_q1[i] = 0.f; }
    if (i < R2P) { g_s2[i] = 0.f; g_q2[i] = 0.f; }
}

// Average the 7 experts for each source; write into concatenated [2816][1536].
__global__ void avg_weights_kernel(const float* __restrict__ pW0,
                                   const float* __restrict__ pW1,
                                   const float* __restrict__ pWib) {
    int idx = threadIdx.x + blockIdx.x * blockDim.x;  // over KTOT*DOUT = 4.3M
    if (idx >= KTOT * DOUT) return;
    int r = idx / DOUT;
    int c = idx - r * DOUT;
    const float* src;
    int lr, d;
    if (r < D0)            { src = pW0;  lr = r;              d = D0;  }
    else if (r < D0 + D1)  { src = pW1;  lr = r - D0;         d = D1;  }
    else                   { src = pWib; lr = r - (D0 + D1);  d = DIB; }
    float s = 0.f;
    #pragma unroll
    for (int e = 0; e < NEXP; e++)
        s += src[(size_t)e * d * DOUT + (size_t)lr * DOUT + c];
    g_Wavg[idx] = s * (1.0f / NEXP);
}

__global__ void avg_bias_kernel(const float* __restrict__ pb0,
                                const float* __restrict__ pb1,
                                const float* __restrict__ pbib) {
    int idx = threadIdx.x + blockIdx.x * blockDim.x;  // 3*1536
    if (idx >= 3 * DOUT) return;
    int seg = idx / DOUT;
    int c = idx - seg * DOUT;
    const float* src = (seg == 0) ? pb0 : (seg == 1) ? pb1 : pbib;
    float s = 0.f;
    #pragma unroll
    for (int e = 0; e < NEXP; e++) s += src[e * DOUT + c];
    g_bavg[idx] = s * (1.0f / NEXP);
}

__global__ void pad_rw2_kernel(const float* __restrict__ rw2,
                               const float* __restrict__ rb2) {
    int idx = threadIdx.x + blockIdx.x * blockDim.x;  // R1N*R2P
    if (idx < R1N * R2P) {
        int r = idx / R2P;
        int c = idx - r * R2P;
        g_rw2p[idx] = (c < R2N) ? rw2[r * R2N + c] : 0.f;
    }
    if (idx < R2P) g_rb2p[idx] = (idx < R2N) ? rb2[idx] : 0.f;
}

// ---- generic fp32 tiled GEMM: C[M,N] = A[M,K] @ B[K,N] (+ bias) ----
// M,N multiples of 128; K multiple of 16. 256 threads, 8x8 per thread.
#define GBM 128
#define GBN 128
#define GBK 16
__global__ __launch_bounds__(256)
void sgemm_kernel(const float* __restrict__ A, const float* __restrict__ B,
                  const float* __restrict__ bias, float* __restrict__ C,
                  int M, int N, int K) {
    __shared__ float As[GBK][GBM + 4];
    __shared__ float Bs[GBK][GBN];
    const int tid  = threadIdx.x;
    const int bm   = blockIdx.y * GBM;
    const int bn   = blockIdx.x * GBN;
    const int tcol = (tid & 15) << 3;   // 0..120
    const int trow = (tid >> 4) << 3;   // 0..120
    float acc[8][8] = {};
    const float* Aptr = A + (size_t)bm * K;
    const float* Bptr = B + bn;

    for (int k0 = 0; k0 < K; k0 += GBK) {
        // load A tile 128x16 (512 float4s; 2 per thread), store transposed
        #pragma unroll
        for (int i = 0; i < 2; i++) {
            int li = tid + i * 256;
            int r  = li >> 2;
            int c  = (li & 3) << 2;
            float4 v = *(const float4*)(Aptr + (size_t)r * K + k0 + c);
            As[c + 0][r] = v.x; As[c + 1][r] = v.y;
            As[c + 2][r] = v.z; As[c + 3][r] = v.w;
        }
        // load B tile 16x128
        #pragma unroll
        for (int i = 0; i < 2; i++) {
            int li = tid + i * 256;
            int r  = li >> 5;
            int c  = (li & 31) << 2;
            *(float4*)&Bs[r][c] = *(const float4*)(Bptr + (size_t)(k0 + r) * N + c);
        }
        __syncthreads();
        #pragma unroll
        for (int k = 0; k < GBK; k++) {
            float a[8], b[8];
            #pragma unroll
            for (int i = 0; i < 8; i++) a[i] = As[k][trow + i];
            #pragma unroll
            for (int j = 0; j < 8; j++) b[j] = Bs[k][tcol + j];
            #pragma unroll
            for (int i = 0; i < 8; i++)
                #pragma unroll
                for (int j = 0; j < 8; j++)
                    acc[i][j] = fmaf(a[i], b[j], acc[i][j]);
        }
        __syncthreads();
    }
    #pragma unroll
    for (int i = 0; i < 8; i++) {
        size_t row = (size_t)(bm + trow + i);
        #pragma unroll
        for (int j = 0; j < 8; j += 4) {
            int cc = bn + tcol + j;
            float4 v;
            v.x = acc[i][j + 0]; v.y = acc[i][j + 1];
            v.z = acc[i][j + 2]; v.w = acc[i][j + 3];
            if (bias) {
                v.x += bias[cc];     v.y += bias[cc + 1];
                v.z += bias[cc + 2]; v.w += bias[cc + 3];
            }
            *(float4*)&C[row * N + cc] = v;
        }
    }
}

// column sum / sumsq over BSZ rows (atomic partials over row chunks)
#define STAT_ROWS 256
__global__ void colstats_kernel(const float* __restrict__ H, int Nstride, int N,
                                float* __restrict__ s, float* __restrict__ q) {
    int c = threadIdx.x + blockIdx.x * blockDim.x;
    if (c >= N) return;
    int r0 = blockIdx.y * STAT_ROWS;
    float sum = 0.f, sq = 0.f;
    for (int r = r0; r < r0 + STAT_ROWS; r++) {
        float v = H[(size_t)r * Nstride + c];
        sum += v; sq += v * v;
    }
    atomicAdd(&s[c], sum);
    atomicAdd(&q[c], sq);
}

// in-place batchnorm (training-mode batch stats) + activation (0=relu, 1=tanh)
__global__ void bn_act_kernel(float* __restrict__ H, int Nstride, int N,
                              const float* __restrict__ s, const float* __restrict__ q,
                              const float* __restrict__ g, const float* __restrict__ bt,
                              int act) {
    int idx = threadIdx.x + blockIdx.x * blockDim.x;
    if (idx >= BSZ * Nstride) return;
    int c = idx % Nstride;
    if (c >= N) return;
    float mean = s[c] * (1.0f / BSZ);
    float var  = q[c] * (1.0f / BSZ) - mean * mean;
    float rstd = rsqrtf(var + BN_EPS);
    float v = g[c] * (H[idx] - mean) * rstd + bt[c];
    H[idx] = (act == 0) ? fmaxf(v, 0.f) : tanhf(v);
}

// final router stage: H2n[100] @ rw3[100,3] + rb3 -> sigmoid -> softmax -> g_w
__global__ void router3_kernel(const float* __restrict__ rw3,
                               const float* __restrict__ rb3) {
    __shared__ float W[R2N * 3];
    __shared__ float bb[3];
    int t = threadIdx.x;
    for (int i = t; i < R2N * 3; i += blockDim.x) W[i] = rw3[i];
    if (t < 3) bb[t] = rb3[t];
    __syncthreads();
    int b = blockIdx.x * blockDim.x + t;
    if (b >= BSZ) return;
    const float* h = &g_H2[(size_t)b * R2P];
    float l0 = bb[0], l1 = bb[1], l2 = bb[2];
    #pragma unroll 4
    for (int k = 0; k < R2N; k++) {
        float hv = h[k];
        l0 = fmaf(hv, W[k * 3 + 0], l0);
        l1 = fmaf(hv, W[k * 3 + 1], l1);
        l2 = fmaf(hv, W[k * 3 + 2], l2);
    }
    float s0 = 1.f / (1.f + expf(-l0));
    float s1 = 1.f / (1.f + expf(-l1));
    float s2 = 1.f / (1.f + expf(-l2));
    float e0 = expf(s0), e1 = expf(s1), e2 = expf(s2);
    float inv = 1.f / (e0 + e1 + e2);
    g_w[b * 3 + 0] = e0 * inv;
    g_w[b * 3 + 1] = e1 * inv;
    g_w[b * 3 + 2] = e2 * inv;
}

// Xs[b, :] = [w0*x0[b], w1*x1[b], w2*xib[b]]
__global__ void prep_xs_kernel(const float* __restrict__ x0,
                               const float* __restrict__ x1,
                               const float* __restrict__ xib) {
    int idx = threadIdx.x + blockIdx.x * blockDim.x;  // BSZ*KTOT = 23M
    if (idx >= BSZ * KTOT) return;
    int b = idx / KTOT;
    int c = idx - b * KTOT;
    float v, wt;
    if (c < D0)            { v = x0 [(size_t)b * D0  + c];             wt = g_w[b * 3 + 0]; }
    else if (c < D0 + D1)  { v = x1 [(size_t)b * D1  + (c - D0)];      wt = g_w[b * 3 + 1]; }
    else                   { v = xib[(size_t)b * DIB + (c - D0 - D1)]; wt = g_w[b * 3 + 2]; }
    g_Xs[idx] = v * wt;
}

// in-place: add weighted bias contribution, L2-normalize each row
__global__ __launch_bounds__(256)
void l2norm_kernel(float* __restrict__ O) {
    int b = blockIdx.x;
    int t = threadIdx.x;
    float w0 = g_w[b * 3 + 0], w1 = g_w[b * 3 + 1], w2 = g_w[b * 3 + 2];
    float v[6];
    float ss = 0.f;
    #pragma unroll
    for (int i = 0; i < 6; i++) {
        int c = t + i * 256;
        float x = O[(size_t)b * DOUT + c]
                + w0 * g_bavg[c] + w1 * g_bavg[DOUT + c] + w2 * g_bavg[2 * DOUT + c];
        v[i] = x;
        ss += x * x;
    }
    __shared__ float red[256];
    red[t] = ss;
    __syncthreads();
    for (int s = 128; s > 0; s >>= 1) {
        if (t < s) red[t] += red[t + s];
        __syncthreads();
    }
    float inv = 1.0f / fmaxf(sqrtf(red[0]), 1e-12f);
    #pragma unroll
    for (int i = 0; i < 6; i++)
        O[(size_t)b * DOUT + t + i * 256] = v[i] * inv;
}

// ---------------- launch ----------------
extern "C" void kernel_launch(void* const* d_in, const int* in_sizes, int n_in,
                              void* d_out, int out_size) {
    const float* x0   = (const float*)d_in[0];
    const float* x1   = (const float*)d_in[1];
    const float* xib  = (const float*)d_in[2];
    const float* pW0  = (const float*)d_in[3];
    const float* pb0  = (const float*)d_in[4];
    const float* pW1  = (const float*)d_in[5];
    const float* pb1  = (const float*)d_in[6];
    const float* pWib = (const float*)d_in[7];
    const float* pbib = (const float*)d_in[8];
    const float* rw1  = (const float*)d_in[9];
    const float* rb1  = (const float*)d_in[10];
    const float* rg1  = (const float*)d_in[11];
    const float* rbt1 = (const float*)d_in[12];
    const float* rw2  = (const float*)d_in[13];
    const float* rb2  = (const float*)d_in[14];
    const float* rg2  = (const float*)d_in[15];
    const float* rbt2 = (const float*)d_in[16];
    const float* rw3  = (const float*)d_in[17];
    const float* rb3  = (const float*)d_in[18];
    float* out = (float*)d_out;

    // device-global symbol addresses are usable directly inside kernels;
    // for the GEMM calls we need raw pointers to the globals:
    // (taking address of __device__ globals in host code is invalid; use kernels
    //  that reference the symbols, and for GEMM pass via cudaGetSymbolAddress-free
    //  trick: small launch-time helper pointers)
    static float *p_Wavg = nullptr, *p_H1 = nullptr, *p_H2 = nullptr,
                 *p_rw2p = nullptr, *p_rb2p = nullptr, *p_Xs = nullptr;
    if (!p_Wavg) {
        cudaGetSymbolAddress((void**)&p_Wavg, g_Wavg);
        cudaGetSymbolAddress((void**)&p_H1,   g_H1);
        cudaGetSymbolAddress((void**)&p_H2,   g_H2);
        cudaGetSymbolAddress((void**)&p_rw2p, g_rw2p);
        cudaGetSymbolAddress((void**)&p_rb2p, g_rb2p);
        cudaGetSymbolAddress((void**)&p_Xs,   g_Xs);
    }
    static float *p_s1 = nullptr, *p_q1, *p_s2, *p_q2;
    if (!p_s1) {
        cudaGetSymbolAddress((void**)&p_s1, g_s1);
        cudaGetSymbolAddress((void**)&p_q1, g_q1);
        cudaGetSymbolAddress((void**)&p_s2, g_s2);
        cudaGetSymbolAddress((void**)&p_q2, g_q2);
    }

    // 1. zero BN stat accumulators
    zero_stats_kernel<<<2, 256>>>();

    // 2. average expert weights + biases (independent of router)
    avg_weights_kernel<<<(KTOT * DOUT + 255) / 256, 256>>>(pW0, pW1, pWib);
    avg_bias_kernel<<<(3 * DOUT + 255) / 256, 256>>>(pb0, pb1, pbib);
    pad_rw2_kernel<<<(R1N * R2P + 255) / 256, 256>>>(rw2, rb2);

    // 3. router layer 1: H1 = x0 @ rw1 + rb1
    {
        dim3 grid(R1N / GBN, BSZ / GBM);
        sgemm_kernel<<<grid, 256>>>(x0, rw1, rb1, p_H1, BSZ, R1N, D0);
    }
    {
        dim3 grid((R1N + 255) / 256, BSZ / STAT_ROWS);
        colstats_kernel<<<grid, 256>>>(p_H1, R1N, R1N, p_s1, p_q1);
    }
    bn_act_kernel<<<(BSZ * R1N + 255) / 256, 256>>>(p_H1, R1N, R1N, p_s1, p_q1, rg1, rbt1, 0);

    // 4. router layer 2: H2 = H1n @ rw2p + rb2p   (N padded to 128)
    {
        dim3 grid(R2P / GBN, BSZ / GBM);
        sgemm_kernel<<<grid, 256>>>(p_H1, p_rw2p, p_rb2p, p_H2, BSZ, R2P, R1N);
    }
    {
        dim3 grid(1, BSZ / STAT_ROWS);
        colstats_kernel<<<grid, 256>>>(p_H2, R2P, R2N, p_s2, p_q2);
    }
    bn_act_kernel<<<(BSZ * R2P + 255) / 256, 256>>>(p_H2, R2P, R2N, p_s2, p_q2, rg2, rbt2, 1);

    // 5. router layer 3 + sigmoid + softmax
    router3_kernel<<<BSZ / 256, 256>>>(rw3, rb3);

    // 6. scale + concat inputs by router weight
    prep_xs_kernel<<<(BSZ * KTOT + 255) / 256, 256>>>(x0, x1, xib);

    // 7. main GEMM: out = Xs @ Wavg
    {
        dim3 grid(DOUT / GBN, BSZ / GBM);
        sgemm_kernel<<<grid, 256>>>(p_Xs, p_Wavg, nullptr, out, BSZ, DOUT, KTOT);
    }

    // 8. bias contribution + L2 normalize rows (in-place on out)
    l2norm_kernel<<<BSZ, 256>>>(out);
}

// round 2
// speedup vs baseline: 2.5214x; 2.5214x over previous
#include <cuda_runtime.h>
#include <math.h>
#include <stdint.h>

// ---------------- problem dimensions ----------------
#define BSZ   8192
#define D0    1024
#define D1    768
#define DIB   1024
#define KTOT  2816      // D0 + D1 + DIB
#define DOUT  1536
#define R1N   512
#define R2N   100
#define R2P   128       // padded
#define NEXP  7
#define BN_EPS 1e-5f

// ---------------- scratch (device globals; no allocation allowed) -----------
__device__ float g_Wavg[KTOT * DOUT];        // averaged, concatenated weights [2816][1536]
__device__ float g_bavg[3 * DOUT];           // averaged biases per segment
__device__ float g_H1[BSZ * R1N];            // router hidden 1 (in-place BN+relu)
__device__ float g_H2[BSZ * R2P];            // router hidden 2 (padded to 128)
__device__ float g_rw2p[R1N * R2P];          // padded rw2
__device__ float g_rb2p[R2P];
__device__ float g_s1[R1N], g_q1[R1N];       // col sum / sumsq for BN1
__device__ float g_s2[R2P], g_q2[R2P];       // col sum / sumsq for BN2
__device__ float g_w[BSZ * 3];               // router weights

// ---------------- small helpers ----------------
__device__ __forceinline__ uint32_t f2tf(float x) {
    uint32_t r;
    asm("cvt.rna.tf32.f32 %0, %1;" : "=r"(r) : "f"(x));
    return r;
}

__device__ __forceinline__ void mma8(float* c, const uint32_t* a, const uint32_t* b) {
    asm volatile(
        "mma.sync.aligned.m16n8k8.row.col.f32.tf32.tf32.f32 "
        "{%0,%1,%2,%3},{%4,%5,%6,%7},{%8,%9},{%0,%1,%2,%3};\n"
        : "+f"(c[0]), "+f"(c[1]), "+f"(c[2]), "+f"(c[3])
        : "r"(a[0]), "r"(a[1]), "r"(a[2]), "r"(a[3]), "r"(b[0]), "r"(b[1]));
}

// ---------------- TF32 tensor-core GEMM ----------------
// C[M,N] = A[M,K] @ B[K,N] (+bias). M,N mult of 128, K mult of 32.
// FUSE=1: A is assembled on the fly from [w0*x0 | w1*x1 | w2*xib] (main GEMM).
// BM=BN=128, BK=32; 8 warps, each 64x32 via m16n8k8 tf32 mma.
template<int FUSE>
__global__ __launch_bounds__(256, 2)
void tf32_gemm_kernel(const float* __restrict__ A,
                      const float* __restrict__ B,
                      const float* __restrict__ bias,
                      float* __restrict__ C,
                      int M, int N, int K,
                      const float* __restrict__ x0,
                      const float* __restrict__ x1,
                      const float* __restrict__ xib,
                      const float* __restrict__ w) {
    __shared__ uint32_t As[32 * 128];   // addr: k*128 + (m ^ ((k&3)<<3) ^ ((k>>2)<<2))
    __shared__ uint32_t Bs[32 * 128];   // addr: k*128 + (n ^ ((k&3)<<3))

    const int tid   = threadIdx.x;
    const int warp  = tid >> 5;
    const int lane  = tid & 31;
    const int group = lane >> 2;
    const int tig   = lane & 3;
    const int wm    = (warp & 1) * 64;      // warp M offset in block
    const int wn    = (warp >> 1) * 32;     // warp N offset in block
    const int bm    = blockIdx.y * 128;
    const int bn    = blockIdx.x * 128;

    float acc[4][4][4];
    #pragma unroll
    for (int i = 0; i < 4; i++)
        #pragma unroll
        for (int j = 0; j < 4; j++)
            #pragma unroll
            for (int l = 0; l < 4; l++) acc[i][j][l] = 0.f;

    for (int k0 = 0; k0 < K; k0 += 32) {
        // ---- A tile: 128 rows x 32 k, stored k-major with XOR swizzle ----
        const float* srcA;
        int ldA, kloc, segi = 0;
        if (FUSE) {
            if (k0 < D0)            { srcA = x0;  ldA = D0;  kloc = k0;            segi = 0; }
            else if (k0 < D0 + D1)  { srcA = x1;  ldA = D1;  kloc = k0 - D0;       segi = 1; }
            else                    { srcA = xib; ldA = DIB; kloc = k0 - D0 - D1;  segi = 2; }
        } else {
            srcA = A; ldA = K; kloc = k0;
        }
        #pragma unroll
        for (int i = 0; i < 4; i++) {
            int idx = tid + i * 256;
            int c4  = idx & 7;          // k-quad 0..7
            int r   = idx >> 3;         // row 0..127
            float4 v = *(const float4*)(srcA + (size_t)(bm + r) * ldA + kloc + c4 * 4);
            if (FUSE) {
                float sc = w[(bm + r) * 3 + segi];
                v.x *= sc; v.y *= sc; v.z *= sc; v.w *= sc;
            }
            int kb = c4 * 4;
            // swizzle(k=kb+j, m=r): (j<<3) ^ (c4<<2)  — conflict-free store & load
            As[(kb + 0) * 128 + (r ^ (0 << 3) ^ (c4 << 2))] = f2tf(v.x);
            As[(kb + 1) * 128 + (r ^ (1 << 3) ^ (c4 << 2))] = f2tf(v.y);
            As[(kb + 2) * 128 + (r ^ (2 << 3) ^ (c4 << 2))] = f2tf(v.z);
            As[(kb + 3) * 128 + (r ^ (3 << 3) ^ (c4 << 2))] = f2tf(v.w);
        }
        // ---- B tile: 32 k-rows x 128 n ----
        #pragma unroll
        for (int i = 0; i < 4; i++) {
            int idx = tid + i * 256;
            int c4  = idx & 31;         // n-quad 0..31
            int r   = idx >> 5;         // k-row 0..31
            float4 v = *(const float4*)(B + (size_t)(k0 + r) * N + bn + c4 * 4);
            uint4 t;
            t.x = f2tf(v.x); t.y = f2tf(v.y); t.z = f2tf(v.z); t.w = f2tf(v.w);
            int col = (c4 * 4) ^ ((r & 3) << 3);
            *(uint4*)&Bs[r * 128 + col] = t;
        }
        __syncthreads();

        #pragma unroll
        for (int ks = 0; ks < 4; ks++) {
            uint32_t af[4][4], bf[4][2];
            const int kA     = ks * 8 + tig;           // k of a0/a1 (kA&3 == tig)
            const int row_lo = kA * 128;
            const int row_hi = (kA + 4) * 128;
            const int swa_lo = (tig << 3) ^ (((2 * ks)     & 7) << 2);
            const int swa_hi = (tig << 3) ^ (((2 * ks + 1) & 7) << 2);
            const int swb    = tig << 3;
            #pragma unroll
            for (int mt = 0; mt < 4; mt++) {
                int m0 = wm + mt * 16 + group;
                af[mt][0] = As[row_lo + ( m0      ^ swa_lo)];
                af[mt][1] = As[row_lo + ((m0 + 8) ^ swa_lo)];
                af[mt][2] = As[row_hi + ( m0      ^ swa_hi)];
                af[mt][3] = As[row_hi + ((m0 + 8) ^ swa_hi)];
            }
            #pragma unroll
            for (int nt = 0; nt < 4; nt++) {
                int n0 = wn + nt * 8 + group;
                bf[nt][0] = Bs[row_lo + (n0 ^ swb)];
                bf[nt][1] = Bs[row_hi + (n0 ^ swb)];
            }
            #pragma unroll
            for (int mt = 0; mt < 4; mt++)
                #pragma unroll
                for (int nt = 0; nt < 4; nt++)
                    mma8(acc[mt][nt], af[mt], bf[nt]);
        }
        __syncthreads();
    }

    // ---- epilogue ----
    #pragma unroll
    for (int mt = 0; mt < 4; mt++) {
        int row = bm + wm + mt * 16 + group;
        #pragma unroll
        for (int nt = 0; nt < 4; nt++) {
            int col = bn + wn + nt * 8 + tig * 2;
            float b0v = 0.f, b1v = 0.f;
            if (bias) { b0v = bias[col]; b1v = bias[col + 1]; }
            float2 v0, v1;
            v0.x = acc[mt][nt][0] + b0v; v0.y = acc[mt][nt][1] + b1v;
            v1.x = acc[mt][nt][2] + b0v; v1.y = acc[mt][nt][3] + b1v;
            *(float2*)&C[(size_t)row * N + col]       = v0;
            *(float2*)&C[(size_t)(row + 8) * N + col] = v1;
        }
    }
}

// ---------------- supporting kernels (unchanged from R1) ----------------

__global__ void zero_stats_kernel() {
    int i = threadIdx.x + blockIdx.x * blockDim.x;
    if (i < R1N) { g_s1[i] = 0.f; g_q1[i] = 0.f; }
    if (i < R2P) { g_s2[i] = 0.f; g_q2[i] = 0.f; }
}

__global__ void avg_weights_kernel(const float* __restrict__ pW0,
                                   const float* __restrict__ pW1,
                                   const float* __restrict__ pWib) {
    int idx = threadIdx.x + blockIdx.x * blockDim.x;
    if (idx >= KTOT * DOUT) return;
    int r = idx / DOUT;
    int c = idx - r * DOUT;
    const float* src;
    int lr, d;
    if (r < D0)            { src = pW0;  lr = r;              d = D0;  }
    else if (r < D0 + D1)  { src = pW1;  lr = r - D0;         d = D1;  }
    else                   { src = pWib; lr = r - (D0 + D1);  d = DIB; }
    float s = 0.f;
    #pragma unroll
    for (int e = 0; e < NEXP; e++)
        s += src[(size_t)e * d * DOUT + (size_t)lr * DOUT + c];
    g_Wavg[idx] = s * (1.0f / NEXP);
}

__global__ void avg_bias_kernel(const float* __restrict__ pb0,
                                const float* __restrict__ pb1,
                                const float* __restrict__ pbib) {
    int idx = threadIdx.x + blockIdx.x * blockDim.x;
    if (idx >= 3 * DOUT) return;
    int seg = idx / DOUT;
    int c = idx - seg * DOUT;
    const float* src = (seg == 0) ? pb0 : (seg == 1) ? pb1 : pbib;
    float s = 0.f;
    #pragma unroll
    for (int e = 0; e < NEXP; e++) s += src[e * DOUT + c];
    g_bavg[idx] = s * (1.0f / NEXP);
}

__global__ void pad_rw2_kernel(const float* __restrict__ rw2,
                               const float* __restrict__ rb2) {
    int idx = threadIdx.x + blockIdx.x * blockDim.x;
    if (idx < R1N * R2P) {
        int r = idx / R2P;
        int c = idx - r * R2P;
        g_rw2p[idx] = (c < R2N) ? rw2[r * R2N + c] : 0.f;
    }
    if (idx < R2P) g_rb2p[idx] = (idx < R2N) ? rb2[idx] : 0.f;
}

#define STAT_ROWS 256
__global__ void colstats_kernel(const float* __restrict__ H, int Nstride, int N,
                                float* __restrict__ s, float* __restrict__ q) {
    int c = threadIdx.x + blockIdx.x * blockDim.x;
    if (c >= N) return;
    int r0 = blockIdx.y * STAT_ROWS;
    float sum = 0.f, sq = 0.f;
    for (int r = r0; r < r0 + STAT_ROWS; r++) {
        float v = H[(size_t)r * Nstride + c];
        sum += v; sq += v * v;
    }
    atomicAdd(&s[c], sum);
    atomicAdd(&q[c], sq);
}

__global__ void bn_act_kernel(float* __restrict__ H, int Nstride, int N,
                              const float* __restrict__ s, const float* __restrict__ q,
                              const float* __restrict__ g, const float* __restrict__ bt,
                              int act) {
    int idx = threadIdx.x + blockIdx.x * blockDim.x;
    if (idx >= BSZ * Nstride) return;
    int c = idx % Nstride;
    if (c >= N) return;
    float mean = s[c] * (1.0f / BSZ);
    float var  = q[c] * (1.0f / BSZ) - mean * mean;
    float rstd = rsqrtf(var + BN_EPS);
    float v = g[c] * (H[idx] - mean) * rstd + bt[c];
    H[idx] = (act == 0) ? fmaxf(v, 0.f) : tanhf(v);
}

__global__ void router3_kernel(const float* __restrict__ rw3,
                               const float* __restrict__ rb3) {
    __shared__ float W[R2N * 3];
    __shared__ float bb[3];
    int t = threadIdx.x;
    for (int i = t; i < R2N * 3; i += blockDim.x) W[i] = rw3[i];
    if (t < 3) bb[t] = rb3[t];
    __syncthreads();
    int b = blockIdx.x * blockDim.x + t;
    if (b >= BSZ) return;
    const float* h = &g_H2[(size_t)b * R2P];
    float l0 = bb[0], l1 = bb[1], l2 = bb[2];
    #pragma unroll 4
    for (int k = 0; k < R2N; k++) {
        float hv = h[k];
        l0 = fmaf(hv, W[k * 3 + 0], l0);
        l1 = fmaf(hv, W[k * 3 + 1], l1);
        l2 = fmaf(hv, W[k * 3 + 2], l2);
    }
    float s0 = 1.f / (1.f + expf(-l0));
    float s1 = 1.f / (1.f + expf(-l1));
    float s2 = 1.f / (1.f + expf(-l2));
    float e0 = expf(s0), e1 = expf(s1), e2 = expf(s2);
    float inv = 1.f / (e0 + e1 + e2);
    g_w[b * 3 + 0] = e0 * inv;
    g_w[b * 3 + 1] = e1 * inv;
    g_w[b * 3 + 2] = e2 * inv;
}

__global__ __launch_bounds__(256)
void l2norm_kernel(float* __restrict__ O) {
    int b = blockIdx.x;
    int t = threadIdx.x;
    float w0 = g_w[b * 3 + 0], w1 = g_w[b * 3 + 1], w2 = g_w[b * 3 + 2];
    float v[6];
    float ss = 0.f;
    #pragma unroll
    for (int i = 0; i < 6; i++) {
        int c = t + i * 256;
        float x = O[(size_t)b * DOUT + c]
                + w0 * g_bavg[c] + w1 * g_bavg[DOUT + c] + w2 * g_bavg[2 * DOUT + c];
        v[i] = x;
        ss += x * x;
    }
    __shared__ float red[256];
    red[t] = ss;
    __syncthreads();
    for (int s = 128; s > 0; s >>= 1) {
        if (t < s) red[t] += red[t + s];
        __syncthreads();
    }
    float inv = 1.0f / fmaxf(sqrtf(red[0]), 1e-12f);
    #pragma unroll
    for (int i = 0; i < 6; i++)
        O[(size_t)b * DOUT + t + i * 256] = v[i] * inv;
}

// ---------------- launch ----------------
extern "C" void kernel_launch(void* const* d_in, const int* in_sizes, int n_in,
                              void* d_out, int out_size) {
    const float* x0   = (const float*)d_in[0];
    const float* x1   = (const float*)d_in[1];
    const float* xib  = (const float*)d_in[2];
    const float* pW0  = (const float*)d_in[3];
    const float* pb0  = (const float*)d_in[4];
    const float* pW1  = (const float*)d_in[5];
    const float* pb1  = (const float*)d_in[6];
    const float* pWib = (const float*)d_in[7];
    const float* pbib = (const float*)d_in[8];
    const float* rw1  = (const float*)d_in[9];
    const float* rb1  = (const float*)d_in[10];
    const float* rg1  = (const float*)d_in[11];
    const float* rbt1 = (const float*)d_in[12];
    const float* rw2  = (const float*)d_in[13];
    const float* rb2  = (const float*)d_in[14];
    const float* rg2  = (const float*)d_in[15];
    const float* rbt2 = (const float*)d_in[16];
    const float* rw3  = (const float*)d_in[17];
    const float* rb3  = (const float*)d_in[18];
    float* out = (float*)d_out;

    static float *p_Wavg = nullptr, *p_H1 = nullptr, *p_H2 = nullptr,
                 *p_rw2p = nullptr, *p_rb2p = nullptr, *p_w = nullptr;
    static float *p_s1 = nullptr, *p_q1 = nullptr, *p_s2 = nullptr, *p_q2 = nullptr;
    if (!p_Wavg) {
        cudaGetSymbolAddress((void**)&p_Wavg, g_Wavg);
        cudaGetSymbolAddress((void**)&p_H1,   g_H1);
        cudaGetSymbolAddress((void**)&p_H2,   g_H2);
        cudaGetSymbolAddress((void**)&p_rw2p, g_rw2p);
        cudaGetSymbolAddress((void**)&p_rb2p, g_rb2p);
        cudaGetSymbolAddress((void**)&p_w,    g_w);
        cudaGetSymbolAddress((void**)&p_s1,   g_s1);
        cudaGetSymbolAddress((void**)&p_q1,   g_q1);
        cudaGetSymbolAddress((void**)&p_s2,   g_s2);
        cudaGetSymbolAddress((void**)&p_q2,   g_q2);
    }

    // 1. zero BN stat accumulators
    zero_stats_kernel<<<2, 256>>>();

    // 2. average expert weights + biases, pad rw2
    avg_weights_kernel<<<(KTOT * DOUT + 255) / 256, 256>>>(pW0, pW1, pWib);
    avg_bias_kernel<<<(3 * DOUT + 255) / 256, 256>>>(pb0, pb1, pbib);
    pad_rw2_kernel<<<(R1N * R2P + 255) / 256, 256>>>(rw2, rb2);

    // 3. router layer 1: H1 = x0 @ rw1 + rb1  (tf32 tensor cores)
    {
        dim3 grid(R1N / 128, BSZ / 128);
        tf32_gemm_kernel<0><<<grid, 256>>>(x0, rw1, rb1, p_H1, BSZ, R1N, D0,
                                           nullptr, nullptr, nullptr, nullptr);
    }
    {
        dim3 grid((R1N + 255) / 256, BSZ / STAT_ROWS);
        colstats_kernel<<<grid, 256>>>(p_H1, R1N, R1N, p_s1, p_q1);
    }
    bn_act_kernel<<<(BSZ * R1N + 255) / 256, 256>>>(p_H1, R1N, R1N, p_s1, p_q1, rg1, rbt1, 0);

    // 4. router layer 2: H2 = H1n @ rw2p + rb2p
    {
        dim3 grid(R2P / 128, BSZ / 128);
        tf32_gemm_kernel<0><<<grid, 256>>>(p_H1, p_rw2p, p_rb2p, p_H2, BSZ, R2P, R1N,
                                           nullptr, nullptr, nullptr, nullptr);
    }
    {
        dim3 grid(1, BSZ / STAT_ROWS);
        colstats_kernel<<<grid, 256>>>(p_H2, R2P, R2N, p_s2, p_q2);
    }
    bn_act_kernel<<<(BSZ * R2P + 255) / 256, 256>>>(p_H2, R2P, R2N, p_s2, p_q2, rg2, rbt2, 1);

    // 5. router layer 3 + sigmoid + softmax
    router3_kernel<<<BSZ / 256, 256>>>(rw3, rb3);

    // 6. main GEMM: out = [w0*x0 | w1*x1 | w2*xib] @ Wavg   (A assembled in-kernel)
    {
        dim3 grid(DOUT / 128, BSZ / 128);
        tf32_gemm_kernel<1><<<grid, 256>>>(nullptr, p_Wavg, nullptr, out, BSZ, DOUT, KTOT,
                                           x0, x1, xib, p_w);
    }

    // 7. bias contribution + L2 normalize rows (in-place on out)
    l2norm_kernel<<<BSZ, 256>>>(out);
}

// round 8
// speedup vs baseline: 3.1230x; 1.2386x over previous
#include <cuda_runtime.h>
#include <cuda_fp16.h>
#include <math.h>
#include <stdint.h>

// ---------------- problem dimensions ----------------
#define BSZ   8192
#define D0    1024
#define D1    768
#define DIB   1024
#define KTOT  2816
#define DOUT  1536
#define R1N   512
#define R2N   100
#define R2P   128
#define NEXP  7
#define BN_EPS 1e-5f

// ---------------- scratch ----------------
__device__ __half g_Wh[(size_t)DOUT * KTOT];     // averaged expert weights, transposed [N][K], fp16
__device__ __half g_rw1Th[R1N * D0];             // rw1^T fp16 [512][1024]
__device__ __half g_rw2Th[R2P * R1N];            // rw2^T fp16 [128][512], rows 100..127 zero
__device__ __half g_x0h[(size_t)BSZ * D0];       // x0 fp16
__device__ __half g_H1h[(size_t)BSZ * R1N];      // BN1+relu output fp16
__device__ __half g_Xsh[(size_t)BSZ * KTOT];     // router-scaled concat inputs fp16
__device__ float  g_H1[(size_t)BSZ * R1N];       // router hidden 1 fp32
__device__ float  g_H2[(size_t)BSZ * R2P];       // router hidden 2 fp32
__device__ float  g_bavg[3 * DOUT];
__device__ float  g_rb2p[R2P];
__device__ float  g_s1[R1N], g_q1[R1N];
__device__ float  g_s2[R2P], g_q2[R2P];
__device__ float  g_w[BSZ * 3];

// ---------------- fp16 tensor-core GEMM ----------------
// C[M, Ntot] tile (128x128) = A[128,K] @ BT[128,K]^T.  A,BT fp16 row-major (K-major).
// K multiple of 32. 8 warps, each 64x32 warp tile via mma.m16n8k16.
__device__ __forceinline__ void hmma16(float* c, const uint32_t* a, const uint32_t* b) {
    asm volatile(
        "mma.sync.aligned.m16n8k16.row.col.f32.f16.f16.f32 "
        "{%0,%1,%2,%3},{%4,%5,%6,%7},{%8,%9},{%0,%1,%2,%3};\n"
        : "+f"(c[0]), "+f"(c[1]), "+f"(c[2]), "+f"(c[3])
        : "r"(a[0]), "r"(a[1]), "r"(a[2]), "r"(a[3]), "r"(b[0]), "r"(b[1]));
}

__global__ __launch_bounds__(256)
void hgemm_kernel(const __half* __restrict__ A, const __half* __restrict__ BT,
                  const float* __restrict__ bias, float* __restrict__ C,
                  int Ntot, int K) {
    // SMEM: [buf][k4][m] uint2 (4 halves along k per uint2), XOR swizzle on m
    __shared__ uint2 As[2][8][128];
    __shared__ uint2 Bs[2][8][128];

    const int tid   = threadIdx.x;
    const int warp  = tid >> 5;
    const int lane  = tid & 31;
    const int group = lane >> 2;
    const int tig   = lane & 3;
    const int sel   = tig & 1;
    const int t2    = tig >> 1;
    const int wm    = (warp & 1) * 64;
    const int wn    = (warp >> 1) * 32;
    const int bm    = blockIdx.y * 128;
    const int bn    = blockIdx.x * 128;
    const int NC    = K / 32;

    const int r_ld = tid >> 2;          // 0..63  (row within half-tile per it)
    const int q_ld = tid & 3;           // 0..3   (16B chunk within 64B row)

    float acc[4][4][4];
    #pragma unroll
    for (int i = 0; i < 4; i++)
        #pragma unroll
        for (int j = 0; j < 4; j++)
            #pragma unroll
            for (int l = 0; l < 4; l++) acc[i][j][l] = 0.f;

    uint4 sa[2], sb[2];
    // prologue: load chunk 0
    #pragma unroll
    for (int it = 0; it < 2; it++) {
        int r = r_ld + it * 64;
        sa[it] = *(const uint4*)(A  + (size_t)(bm + r) * K + q_ld * 8);
        sb[it] = *(const uint4*)(BT + (size_t)(bn + r) * K + q_ld * 8);
    }
    {
        const int k40 = 2 * q_ld, k41 = 2 * q_ld + 1;
        const int sw0 = (k40 & 3) << 3, sw1 = (k41 & 3) << 3;
        #pragma unroll
        for (int it = 0; it < 2; it++) {
            int r = r_ld + it * 64;
            As[0][k40][r ^ sw0] = make_uint2(sa[it].x, sa[it].y);
            As[0][k41][r ^ sw1] = make_uint2(sa[it].z, sa[it].w);
            Bs[0][k40][r ^ sw0] = make_uint2(sb[it].x, sb[it].y);
            Bs[0][k41][r ^ sw1] = make_uint2(sb[it].z, sb[it].w);
        }
    }
    __syncthreads();

    for (int c = 0; c < NC; c++) {
        const int buf = c & 1;
        if (c + 1 < NC) {
            const int koff = (c + 1) * 32 + q_ld * 8;
            #pragma unroll
            for (int it = 0; it < 2; it++) {
                int r = r_ld + it * 64;
                sa[it] = *(const uint4*)(A  + (size_t)(bm + r) * K + koff);
                sb[it] = *(const uint4*)(BT + (size_t)(bn + r) * K + koff);
            }
        }

        const uint32_t* As32 = (const uint32_t*)&As[buf][0][0];
        const uint32_t* Bs32 = (const uint32_t*)&Bs[buf][0][0];
        #pragma unroll
        for (int s = 0; s < 2; s++) {
            const int k4a = 4 * s + t2;
            const int k4b = k4a + 2;
            const int swa = (k4a & 3) << 3;
            const int swb = (k4b & 3) << 3;
            const int rowa = k4a << 7, rowb = k4b << 7;
            uint32_t af[4][4], bf[4][2];
            #pragma unroll
            for (int mt = 0; mt < 4; mt++) {
                int m0 = wm + mt * 16 + group;
                af[mt][0] = As32[((rowa + ( m0      ^ swa)) << 1) + sel];
                af[mt][1] = As32[((rowa + ((m0 + 8) ^ swa)) << 1) + sel];
                af[mt][2] = As32[((rowb + ( m0      ^ swb)) << 1) + sel];
                af[mt][3] = As32[((rowb + ((m0 + 8) ^ swb)) << 1) + sel];
            }
            #pragma unroll
            for (int nt = 0; nt < 4; nt++) {
                int n0 = wn + nt * 8 + group;
                bf[nt][0] = Bs32[((rowa + (n0 ^ swa)) << 1) + sel];
                bf[nt][1] = Bs32[((rowb + (n0 ^ swb)) << 1) + sel];
            }
            #pragma unroll
            for (int mt = 0; mt < 4; mt++)
                #pragma unroll
                for (int nt = 0; nt < 4; nt++)
                    hmma16(acc[mt][nt], af[mt], bf[nt]);
        }

        if (c + 1 < NC) {
            const int nb = (c + 1) & 1;
            const int k40 = 2 * q_ld, k41 = 2 * q_ld + 1;
            const int sw0 = (k40 & 3) << 3, sw1 = (k41 & 3) << 3;
            #pragma unroll
            for (int it = 0; it < 2; it++) {
                int r = r_ld + it * 64;
                As[nb][k40][r ^ sw0] = make_uint2(sa[it].x, sa[it].y);
                As[nb][k41][r ^ sw1] = make_uint2(sa[it].z, sa[it].w);
                Bs[nb][k40][r ^ sw0] = make_uint2(sb[it].x, sb[it].y);
                Bs[nb][k41][r ^ sw1] = make_uint2(sb[it].z, sb[it].w);
            }
        }
        __syncthreads();
    }

    // epilogue
    #pragma unroll
    for (int mt = 0; mt < 4; mt++) {
        int row = bm + wm + mt * 16 + group;
        #pragma unroll
        for (int nt = 0; nt < 4; nt++) {
            int col = bn + wn + nt * 8 + tig * 2;
            float b0v = 0.f, b1v = 0.f;
            if (bias) { b0v = bias[col]; b1v = bias[col + 1]; }
            float2 v0, v1;
            v0.x = acc[mt][nt][0] + b0v; v0.y = acc[mt][nt][1] + b1v;
            v1.x = acc[mt][nt][2] + b0v; v1.y = acc[mt][nt][3] + b1v;
            *(float2*)&C[(size_t)row * Ntot + col]       = v0;
            *(float2*)&C[(size_t)(row + 8) * Ntot + col] = v1;
        }
    }
}

// ---------------- prep kernels ----------------

__global__ void zero_stats_kernel(const float* __restrict__ rb2) {
    int i = threadIdx.x + blockIdx.x * blockDim.x;
    if (i < R1N) { g_s1[i] = 0.f; g_q1[i] = 0.f; }
    if (i < R2P) { g_s2[i] = 0.f; g_q2[i] = 0.f; g_rb2p[i] = (i < R2N) ? rb2[i] : 0.f; }
}

// averaged + transposed expert weights -> g_Wh[n][k] fp16
__global__ void wavgT_kernel(const float* __restrict__ pW0,
                             const float* __restrict__ pW1,
                             const float* __restrict__ pWib) {
    __shared__ float t[32][33];
    const int k0 = blockIdx.x * 32, n0 = blockIdx.y * 32;
    const int tx = threadIdx.x, ty = threadIdx.y;  // 32x8
    #pragma unroll
    for (int i = 0; i < 4; i++) {
        int k = k0 + ty + i * 8;
        const float* src; int lr, d;
        if (k < D0)           { src = pW0;  lr = k;            d = D0;  }
        else if (k < D0 + D1) { src = pW1;  lr = k - D0;       d = D1;  }
        else                  { src = pWib; lr = k - D0 - D1;  d = DIB; }
        float s = 0.f;
        #pragma unroll
        for (int e = 0; e < NEXP; e++)
            s += src[(size_t)e * d * DOUT + (size_t)lr * DOUT + n0 + tx];
        t[ty + i * 8][tx] = s * (1.0f / NEXP);
    }
    __syncthreads();
    #pragma unroll
    for (int i = 0; i < 4; i++)
        g_Wh[(size_t)(n0 + ty + i * 8) * KTOT + k0 + tx] = __float2half_rn(t[tx][ty + i * 8]);
}

// fp32 [K][N] -> fp16 transposed [NP][K], zero-padded rows n>=N
__global__ void transpose_pad_h_kernel(const float* __restrict__ in, __half* __restrict__ out,
                                       int K, int N) {
    __shared__ float t[32][33];
    const int k0 = blockIdx.x * 32, n0 = blockIdx.y * 32;
    const int tx = threadIdx.x, ty = threadIdx.y;
    #pragma unroll
    for (int i = 0; i < 4; i++) {
        int n = n0 + tx;
        t[ty + i * 8][tx] = (n < N) ? in[(size_t)(k0 + ty + i * 8) * N + n] : 0.f;
    }
    __syncthreads();
    #pragma unroll
    for (int i = 0; i < 4; i++)
        out[(size_t)(n0 + ty + i * 8) * K + k0 + tx] = __float2half_rn(t[tx][ty + i * 8]);
}

__global__ void avg_bias_kernel(const float* __restrict__ pb0,
                                const float* __restrict__ pb1,
                                const float* __restrict__ pbib) {
    int idx = threadIdx.x + blockIdx.x * blockDim.x;
    if (idx >= 3 * DOUT) return;
    int seg = idx / DOUT;
    int c = idx - seg * DOUT;
    const float* src = (seg == 0) ? pb0 : (seg == 1) ? pb1 : pbib;
    float s = 0.f;
    #pragma unroll
    for (int e = 0; e < NEXP; e++) s += src[e * DOUT + c];
    g_bavg[idx] = s * (1.0f / NEXP);
}

// x0 fp32 -> fp16 (vectorized x4)
__global__ void cvt_x0_kernel(const float* __restrict__ x0) {
    int i4 = threadIdx.x + blockIdx.x * blockDim.x;
    if (i4 >= BSZ * D0 / 4) return;
    float4 v = ((const float4*)x0)[i4];
    __half2 o[2];
    o[0] = __floats2half2_rn(v.x, v.y);
    o[1] = __floats2half2_rn(v.z, v.w);
    *(__half2*)(g_x0h + (size_t)i4 * 4)     = o[0];
    *(__half2*)(g_x0h + (size_t)i4 * 4 + 2) = o[1];
}

#define STAT_ROWS 256
__global__ void colstats_kernel(const float* __restrict__ H, int Nstride, int N,
                                float* __restrict__ s, float* __restrict__ q) {
    int c = threadIdx.x + blockIdx.x * blockDim.x;
    if (c >= N) return;
    int r0 = blockIdx.y * STAT_ROWS;
    float sum = 0.f, sq = 0.f;
    for (int r = r0; r < r0 + STAT_ROWS; r++) {
        float v = H[(size_t)r * Nstride + c];
        sum += v; sq += v * v;
    }
    atomicAdd(&s[c], sum);
    atomicAdd(&q[c], sq);
}

// BN1 + relu: fp32 H1 -> fp16 H1h
__global__ void bn_relu_h_kernel(const float* __restrict__ g, const float* __restrict__ bt) {
    int idx = threadIdx.x + blockIdx.x * blockDim.x;
    if (idx >= BSZ * R1N) return;
    int c = idx % R1N;
    float mean = g_s1[c] * (1.0f / BSZ);
    float var  = g_q1[c] * (1.0f / BSZ) - mean * mean;
    float rstd = rsqrtf(var + BN_EPS);
    float v = g[c] * (g_H1[idx] - mean) * rstd + bt[c];
    g_H1h[idx] = __float2half_rn(fmaxf(v, 0.f));
}

// BN2 + tanh in-place on fp32 H2 (cols >= R2N skipped)
__global__ void bn_tanh_kernel(const float* __restrict__ g, const float* __restrict__ bt) {
    int idx = threadIdx.x + blockIdx.x * blockDim.x;
    if (idx >= BSZ * R2P) return;
    int c = idx % R2P;
    if (c >= R2N) return;
    float mean = g_s2[c] * (1.0f / BSZ);
    float var  = g_q2[c] * (1.0f / BSZ) - mean * mean;
    float rstd = rsqrtf(var + BN_EPS);
    float v = g[c] * (g_H2[idx] - mean) * rstd + bt[c];
    g_H2[idx] = tanhf(v);
}

__global__ void router3_kernel(const float* __restrict__ rw3,
                               const float* __restrict__ rb3) {
    __shared__ float W[R2N * 3];
    __shared__ float bb[3];
    int t = threadIdx.x;
    for (int i = t; i < R2N * 3; i += blockDim.x) W[i] = rw3[i];
    if (t < 3) bb[t] = rb3[t];
    __syncthreads();
    int b = blockIdx.x * blockDim.x + t;
    if (b >= BSZ) return;
    const float* h = &g_H2[(size_t)b * R2P];
    float l0 = bb[0], l1 = bb[1], l2 = bb[2];
    #pragma unroll 4
    for (int k = 0; k < R2N; k++) {
        float hv = h[k];
        l0 = fmaf(hv, W[k * 3 + 0], l0);
        l1 = fmaf(hv, W[k * 3 + 1], l1);
        l2 = fmaf(hv, W[k * 3 + 2], l2);
    }
    float s0 = 1.f / (1.f + expf(-l0));
    float s1 = 1.f / (1.f + expf(-l1));
    float s2 = 1.f / (1.f + expf(-l2));
    float e0 = expf(s0), e1 = expf(s1), e2 = expf(s2);
    float inv = 1.f / (e0 + e1 + e2);
    g_w[b * 3 + 0] = e0 * inv;
    g_w[b * 3 + 1] = e1 * inv;
    g_w[b * 3 + 2] = e2 * inv;
}

// Xs[b,:] = fp16([w0*x0[b] | w1*x1[b] | w2*xib[b]])  (vectorized x4)
__global__ void xs_prep_kernel(const float* __restrict__ x0,
                               const float* __restrict__ x1,
                               const float* __restrict__ xib) {
    int i4 = threadIdx.x + blockIdx.x * blockDim.x;
    if (i4 >= BSZ * KTOT / 4) return;
    int idx = i4 * 4;
    int b = idx / KTOT;
    int c = idx - b * KTOT;
    const float* src;
    int off, segi;
    if (c < D0)           { src = x0  + (size_t)b * D0;  off = c;            segi = 0; }
    else if (c < D0 + D1) { src = x1  + (size_t)b * D1;  off = c - D0;       segi = 1; }
    else                  { src = xib + (size_t)b * DIB; off = c - D0 - D1;  segi = 2; }
    float wt = g_w[b * 3 + segi];
    float4 v = *(const float4*)(src + off);
    __half2 o0 = __floats2half2_rn(v.x * wt, v.y * wt);
    __half2 o1 = __floats2half2_rn(v.z * wt, v.w * wt);
    *(__half2*)(g_Xsh + (size_t)i4 * 4)     = o0;
    *(__half2*)(g_Xsh + (size_t)i4 * 4 + 2) = o1;
}

__global__ __launch_bounds__(256)
void l2norm_kernel(float* __restrict__ O) {
    int b = blockIdx.x;
    int t = threadIdx.x;
    float w0 = g_w[b * 3 + 0], w1 = g_w[b * 3 + 1], w2 = g_w[b * 3 + 2];
    float v[6];
    float ss = 0.f;
    #pragma unroll
    for (int i = 0; i < 6; i++) {
        int c = t + i * 256;
        float x = O[(size_t)b * DOUT + c]
                + w0 * g_bavg[c] + w1 * g_bavg[DOUT + c] + w2 * g_bavg[2 * DOUT + c];
        v[i] = x;
        ss += x * x;
    }
    __shared__ float red[256];
    red[t] = ss;
    __syncthreads();
    for (int s = 128; s > 0; s >>= 1) {
        if (t < s) red[t] += red[t + s];
        __syncthreads();
    }
    float inv = 1.0f / fmaxf(sqrtf(red[0]), 1e-12f);
    #pragma unroll
    for (int i = 0; i < 6; i++)
        O[(size_t)b * DOUT + t + i * 256] = v[i] * inv;
}

// ---------------- launch ----------------
extern "C" void kernel_launch(void* const* d_in, const int* in_sizes, int n_in,
                              void* d_out, int out_size) {
    const float* x0   = (const float*)d_in[0];
    const float* x1   = (const float*)d_in[1];
    const float* xib  = (const float*)d_in[2];
    const float* pW0  = (const float*)d_in[3];
    const float* pb0  = (const float*)d_in[4];
    const float* pW1  = (const float*)d_in[5];
    const float* pb1  = (const float*)d_in[6];
    const float* pWib = (const float*)d_in[7];
    const float* pbib = (const float*)d_in[8];
    const float* rw1  = (const float*)d_in[9];
    const float* rb1  = (const float*)d_in[10];
    const float* rg1  = (const float*)d_in[11];
    const float* rbt1 = (const float*)d_in[12];
    const float* rw2  = (const float*)d_in[13];
    const float* rb2  = (const float*)d_in[14];
    const float* rg2  = (const float*)d_in[15];
    const float* rbt2 = (const float*)d_in[16];
    const float* rw3  = (const float*)d_in[17];
    const float* rb3  = (const float*)d_in[18];
    float* out = (float*)d_out;

    static float *p_H1, *p_H2, *p_rb2p, *p_s1, *p_q1, *p_s2, *p_q2;
    static __half *p_Wh, *p_rw1Th, *p_rw2Th, *p_x0h, *p_H1h, *p_Xsh;
    static bool s_init = false;
    if (!s_init) {
        cudaGetSymbolAddress((void**)&p_H1,    g_H1);
        cudaGetSymbolAddress((void**)&p_H2,    g_H2);
        cudaGetSymbolAddress((void**)&p_rb2p,  g_rb2p);
        cudaGetSymbolAddress((void**)&p_s1,    g_s1);
        cudaGetSymbolAddress((void**)&p_q1,    g_q1);
        cudaGetSymbolAddress((void**)&p_s2,    g_s2);
        cudaGetSymbolAddress((void**)&p_q2,    g_q2);
        cudaGetSymbolAddress((void**)&p_Wh,    g_Wh);
        cudaGetSymbolAddress((void**)&p_rw1Th, g_rw1Th);
        cudaGetSymbolAddress((void**)&p_rw2Th, g_rw2Th);
        cudaGetSymbolAddress((void**)&p_x0h,   g_x0h);
        cudaGetSymbolAddress((void**)&p_H1h,   g_H1h);
        cudaGetSymbolAddress((void**)&p_Xsh,   g_Xsh);
        s_init = true;
    }

    // 1. stats zero + rb2 pad
    zero_stats_kernel<<<2, 256>>>(rb2);

    // 2. weight prep (fp16): averaged+transposed experts, transposed router weights, biases, x0h
    wavgT_kernel<<<dim3(KTOT / 32, DOUT / 32), dim3(32, 8)>>>(pW0, pW1, pWib);
    transpose_pad_h_kernel<<<dim3(D0 / 32, R1N / 32), dim3(32, 8)>>>(rw1, p_rw1Th, D0, R1N);
    transpose_pad_h_kernel<<<dim3(R1N / 32, R2P / 32), dim3(32, 8)>>>(rw2, p_rw2Th, R1N, R2N);
    avg_bias_kernel<<<(3 * DOUT + 255) / 256, 256>>>(pb0, pb1, pbib);
    cvt_x0_kernel<<<(BSZ * D0 / 4 + 255) / 256, 256>>>(x0);

    // 3. router layer 1: H1 = x0 @ rw1 + rb1
    hgemm_kernel<<<dim3(R1N / 128, BSZ / 128), 256>>>(p_x0h, p_rw1Th, rb1, p_H1, R1N, D0);
    colstats_kernel<<<dim3((R1N + 255) / 256, BSZ / STAT_ROWS), 256>>>(p_H1, R1N, R1N, p_s1, p_q1);
    bn_relu_h_kernel<<<(BSZ * R1N + 255) / 256, 256>>>(rg1, rbt1);

    // 4. router layer 2: H2 = H1h @ rw2p + rb2p
    hgemm_kernel<<<dim3(1, BSZ / 128), 256>>>(p_H1h, p_rw2Th, p_rb2p, p_H2, R2P, R1N);
    colstats_kernel<<<dim3(1, BSZ / STAT_ROWS), 256>>>(p_H2, R2P, R2N, p_s2, p_q2);
    bn_tanh_kernel<<<(BSZ * R2P + 255) / 256, 256>>>(rg2, rbt2);

    // 5. router layer 3 + sigmoid + softmax
    router3_kernel<<<BSZ / 256, 256>>>(rw3, rb3);

    // 6. Xs = router-scaled concat (fp16)
    xs_prep_kernel<<<(BSZ * KTOT / 4 + 255) / 256, 256>>>(x0, x1, xib);

    // 7. main GEMM: out = Xs @ Wavg^T
    hgemm_kernel<<<dim3(DOUT / 128, BSZ / 128), 256>>>(p_Xsh, p_Wh, nullptr, out, DOUT, KTOT);

    // 8. bias contribution + L2 normalize
    l2norm_kernel<<<BSZ, 256>>>(out);
}

// round 9
// speedup vs baseline: 4.2857x; 1.3723x over previous
#include <cuda_runtime.h>
#include <cuda_fp16.h>
#include <math.h>
#include <stdint.h>

// ---------------- problem dimensions ----------------
#define BSZ   8192
#define D0    1024
#define D1    768
#define DIB   1024
#define KTOT  2816
#define DOUT  1536
#define R1N   512
#define R2N   100
#define R2P   128
#define NEXP  7
#define BN_EPS 1e-5f

// ---------------- scratch ----------------
__device__ __half g_Wh[(size_t)DOUT * KTOT];     // averaged expert weights, transposed [N][K], fp16
__device__ __half g_rw1Th[R1N * D0];             // rw1^T fp16 [512][1024]
__device__ __half g_rw2Th[R2P * R1N];            // rw2^T fp16 [128][512], rows 100..127 zero
__device__ __half g_x0h[(size_t)BSZ * D0];       // x0 fp16
__device__ __half g_H1h[(size_t)BSZ * R1N];      // BN1+relu output fp16
__device__ __half g_Xsh[(size_t)BSZ * KTOT];     // router-scaled concat inputs fp16
__device__ float  g_H1[(size_t)BSZ * R1N];       // router hidden 1 fp32
__device__ float  g_H2[(size_t)BSZ * R2P];       // router hidden 2 fp32
__device__ float  g_bavg[3 * DOUT];
__device__ float  g_rb2p[R2P];
__device__ float  g_s1[R1N], g_q1[R1N];
__device__ float  g_s2[R2P], g_q2[R2P];
__device__ float  g_w[BSZ * 3];

// ---------------- helpers ----------------
__device__ __forceinline__ uint32_t smem_u32(const void* p) {
    uint32_t a;
    asm("{ .reg .u64 t; cvta.to.shared.u64 t, %1; cvt.u32.u64 %0, t; }" : "=r"(a) : "l"(p));
    return a;
}
__device__ __forceinline__ void hmma16(float* c, const uint32_t* a, const uint32_t* b) {
    asm volatile(
        "mma.sync.aligned.m16n8k16.row.col.f32.f16.f16.f32 "
        "{%0,%1,%2,%3},{%4,%5,%6,%7},{%8,%9},{%0,%1,%2,%3};\n"
        : "+f"(c[0]), "+f"(c[1]), "+f"(c[2]), "+f"(c[3])
        : "r"(a[0]), "r"(a[1]), "r"(a[2]), "r"(a[3]), "r"(b[0]), "r"(b[1]));
}
__device__ __forceinline__ void ldsm4(uint32_t* d, uint32_t addr) {
    asm volatile("ldmatrix.sync.aligned.m8n8.x4.shared.b16 {%0,%1,%2,%3}, [%4];"
        : "=r"(d[0]), "=r"(d[1]), "=r"(d[2]), "=r"(d[3]) : "r"(addr));
}

// ---------------- fp16 tensor-core GEMM (ldmatrix + cp.async, 3-stage) ----------------
// C tile 128x128 = A[128,K] @ BT[128,K]^T.  A,BT fp16 K-major. K multiple of 64.
// SMEM per stage: A 128 rows x 64 halves (128B/row), B same. Swizzle: 16B chunk c ^= (row&7).
#define GK 64
#define STAGE_BYTES 32768
__global__ __launch_bounds__(256)
void hgemm_kernel(const __half* __restrict__ A, const __half* __restrict__ BT,
                  const float* __restrict__ bias, float* __restrict__ C,
                  int Ntot, int K) {
    extern __shared__ char smem[];
    const uint32_t sbase = smem_u32(smem);

    const int tid   = threadIdx.x;
    const int warp  = tid >> 5;
    const int lane  = tid & 31;
    const int group = lane >> 2;
    const int tig   = lane & 3;
    const int wm    = (warp & 1) * 64;
    const int wn    = (warp >> 1) * 32;
    const int bm    = blockIdx.y * 128;
    const int bn    = blockIdx.x * 128;
    const int NC    = K / GK;

    const int r_ld  = tid >> 3;         // 0..31 base row for loads (x4 iters -> 128 rows? no: idx>>3)
    const int ch_ld = tid & 7;

    float acc[4][4][4];
    #pragma unroll
    for (int i = 0; i < 4; i++)
        #pragma unroll
        for (int j = 0; j < 4; j++)
            #pragma unroll
            for (int l = 0; l < 4; l++) acc[i][j][l] = 0.f;

    // ---- async chunk loader ----
    auto issue_chunk = [&](int c) {
        const int s = c % 3;
        const uint32_t abase = sbase + s * STAGE_BYTES;
        const uint32_t bbase = abase + 16384;
        const int kb = c * GK;
        #pragma unroll
        for (int it = 0; it < 4; it++) {
            const int idx = tid + it * 256;
            const int r = idx >> 3;
            const int ch = idx & 7;
            const uint32_t so = r * 128 + ((ch ^ (r & 7)) << 4);
            const __half* ga = A  + (size_t)(bm + r) * K + kb + ch * 8;
            const __half* gb = BT + (size_t)(bn + r) * K + kb + ch * 8;
            asm volatile("cp.async.cg.shared.global [%0], [%1], 16;" :: "r"(abase + so), "l"(ga));
            asm volatile("cp.async.cg.shared.global [%0], [%1], 16;" :: "r"(bbase + so), "l"(gb));
        }
        asm volatile("cp.async.commit_group;" ::: "memory");
    };

    issue_chunk(0);
    if (NC > 1) issue_chunk(1);

    // per-thread fragment address components
    const int a_row0 = wm + (lane & 15);        // + mt*16
    const int a_kch  = lane >> 4;               // 0/1 within k16
    const int b_n0   = wn + ((lane >> 4) << 3) + (lane & 7);  // + nth*16
    const int b_kch  = (lane >> 3) & 1;

    for (int c = 0; c < NC; c++) {
        if (c + 1 < NC) asm volatile("cp.async.wait_group 1;" ::: "memory");
        else            asm volatile("cp.async.wait_group 0;" ::: "memory");
        __syncthreads();
        if (c + 2 < NC) issue_chunk(c + 2);

        const uint32_t abase = sbase + (c % 3) * STAGE_BYTES;
        const uint32_t bbase = abase + 16384;

        #pragma unroll
        for (int ks = 0; ks < 4; ks++) {
            uint32_t af[4][4];
            #pragma unroll
            for (int mt = 0; mt < 4; mt++) {
                const int row = a_row0 + mt * 16;
                const int kc  = ks * 2 + a_kch;
                ldsm4(af[mt], abase + row * 128 + ((kc ^ (row & 7)) << 4));
            }
            uint32_t bf[4][2];
            #pragma unroll
            for (int nth = 0; nth < 2; nth++) {
                const int n  = b_n0 + nth * 16;
                const int kc = ks * 2 + b_kch;
                uint32_t t[4];
                ldsm4(t, bbase + n * 128 + ((kc ^ (n & 7)) << 4));
                bf[nth * 2][0] = t[0]; bf[nth * 2][1] = t[1];
                bf[nth * 2 + 1][0] = t[2]; bf[nth * 2 + 1][1] = t[3];
            }
            #pragma unroll
            for (int mt = 0; mt < 4; mt++)
                #pragma unroll
                for (int nn = 0; nn < 4; nn++)
                    hmma16(acc[mt][nn], af[mt], bf[nn]);
        }
    }

    // epilogue
    #pragma unroll
    for (int mt = 0; mt < 4; mt++) {
        int row = bm + wm + mt * 16 + group;
        #pragma unroll
        for (int nn = 0; nn < 4; nn++) {
            int col = bn + wn + nn * 8 + tig * 2;
            float b0v = 0.f, b1v = 0.f;
            if (bias) { b0v = bias[col]; b1v = bias[col + 1]; }
            float2 v0, v1;
            v0.x = acc[mt][nn][0] + b0v; v0.y = acc[mt][nn][1] + b1v;
            v1.x = acc[mt][nn][2] + b0v; v1.y = acc[mt][nn][3] + b1v;
            *(float2*)&C[(size_t)row * Ntot + col]       = v0;
            *(float2*)&C[(size_t)(row + 8) * Ntot + col] = v1;
        }
    }
}

// ---------------- prep kernels ----------------

__global__ void zero_stats_kernel(const float* __restrict__ rb2) {
    int i = threadIdx.x + blockIdx.x * blockDim.x;
    if (i < R1N) { g_s1[i] = 0.f; g_q1[i] = 0.f; }
    if (i < R2P) { g_s2[i] = 0.f; g_q2[i] = 0.f; g_rb2p[i] = (i < R2N) ? rb2[i] : 0.f; }
}

// averaged + transposed expert weights -> g_Wh[n][k] fp16
__global__ void wavgT_kernel(const float* __restrict__ pW0,
                             const float* __restrict__ pW1,
                             const float* __restrict__ pWib) {
    __shared__ float t[32][33];
    const int k0 = blockIdx.x * 32, n0 = blockIdx.y * 32;
    const int tx = threadIdx.x, ty = threadIdx.y;  // 32x8
    #pragma unroll
    for (int i = 0; i < 4; i++) {
        int k = k0 + ty + i * 8;
        const float* src; int lr, d;
        if (k < D0)           { src = pW0;  lr = k;            d = D0;  }
        else if (k < D0 + D1) { src = pW1;  lr = k - D0;       d = D1;  }
        else                  { src = pWib; lr = k - D0 - D1;  d = DIB; }
        float s = 0.f;
        #pragma unroll
        for (int e = 0; e < NEXP; e++)
            s += src[(size_t)e * d * DOUT + (size_t)lr * DOUT + n0 + tx];
        t[ty + i * 8][tx] = s * (1.0f / NEXP);
    }
    __syncthreads();
    #pragma unroll
    for (int i = 0; i < 4; i++)
        g_Wh[(size_t)(n0 + ty + i * 8) * KTOT + k0 + tx] = __float2half_rn(t[tx][ty + i * 8]);
}

// fp32 [K][N] -> fp16 transposed [NP][K], zero-padded rows n>=N
__global__ void transpose_pad_h_kernel(const float* __restrict__ in, __half* __restrict__ out,
                                       int K, int N) {
    __shared__ float t[32][33];
    const int k0 = blockIdx.x * 32, n0 = blockIdx.y * 32;
    const int tx = threadIdx.x, ty = threadIdx.y;
    #pragma unroll
    for (int i = 0; i < 4; i++) {
        int n = n0 + tx;
        t[ty + i * 8][tx] = (n < N) ? in[(size_t)(k0 + ty + i * 8) * N + n] : 0.f;
    }
    __syncthreads();
    #pragma unroll
    for (int i = 0; i < 4; i++)
        out[(size_t)(n0 + ty + i * 8) * K + k0 + tx] = __float2half_rn(t[tx][ty + i * 8]);
}

__global__ void avg_bias_kernel(const float* __restrict__ pb0,
                                const float* __restrict__ pb1,
                                const float* __restrict__ pbib) {
    int idx = threadIdx.x + blockIdx.x * blockDim.x;
    if (idx >= 3 * DOUT) return;
    int seg = idx / DOUT;
    int c = idx - seg * DOUT;
    const float* src = (seg == 0) ? pb0 : (seg == 1) ? pb1 : pbib;
    float s = 0.f;
    #pragma unroll
    for (int e = 0; e < NEXP; e++) s += src[e * DOUT + c];
    g_bavg[idx] = s * (1.0f / NEXP);
}

// x0 fp32 -> fp16 (vectorized x4)
__global__ void cvt_x0_kernel(const float* __restrict__ x0) {
    int i4 = threadIdx.x + blockIdx.x * blockDim.x;
    if (i4 >= BSZ * D0 / 4) return;
    float4 v = ((const float4*)x0)[i4];
    __half2 o0 = __floats2half2_rn(v.x, v.y);
    __half2 o1 = __floats2half2_rn(v.z, v.w);
    *(__half2*)(g_x0h + (size_t)i4 * 4)     = o0;
    *(__half2*)(g_x0h + (size_t)i4 * 4 + 2) = o1;
}

#define STAT_ROWS 256
__global__ void colstats_kernel(const float* __restrict__ H, int Nstride, int N,
                                float* __restrict__ s, float* __restrict__ q) {
    int c = threadIdx.x + blockIdx.x * blockDim.x;
    if (c >= N) return;
    int r0 = blockIdx.y * STAT_ROWS;
    float sum = 0.f, sq = 0.f;
    for (int r = r0; r < r0 + STAT_ROWS; r++) {
        float v = H[(size_t)r * Nstride + c];
        sum += v; sq += v * v;
    }
    atomicAdd(&s[c], sum);
    atomicAdd(&q[c], sq);
}

// BN1 + relu: fp32 H1 -> fp16 H1h
__global__ void bn_relu_h_kernel(const float* __restrict__ g, const float* __restrict__ bt) {
    int idx = threadIdx.x + blockIdx.x * blockDim.x;
    if (idx >= BSZ * R1N) return;
    int c = idx % R1N;
    float mean = g_s1[c] * (1.0f / BSZ);
    float var  = g_q1[c] * (1.0f / BSZ) - mean * mean;
    float rstd = rsqrtf(var + BN_EPS);
    float v = g[c] * (g_H1[idx] - mean) * rstd + bt[c];
    g_H1h[idx] = __float2half_rn(fmaxf(v, 0.f));
}

// BN2 + tanh in-place on fp32 H2 (cols >= R2N skipped)
__global__ void bn_tanh_kernel(const float* __restrict__ g, const float* __restrict__ bt) {
    int idx = threadIdx.x + blockIdx.x * blockDim.x;
    if (idx >= BSZ * R2P) return;
    int c = idx % R2P;
    if (c >= R2N) return;
    float mean = g_s2[c] * (1.0f / BSZ);
    float var  = g_q2[c] * (1.0f / BSZ) - mean * mean;
    float rstd = rsqrtf(var + BN_EPS);
    float v = g[c] * (g_H2[idx] - mean) * rstd + bt[c];
    g_H2[idx] = tanhf(v);
}

__global__ void router3_kernel(const float* __restrict__ rw3,
                               const float* __restrict__ rb3) {
    __shared__ float W[R2N * 3];
    __shared__ float bb[3];
    int t = threadIdx.x;
    for (int i = t; i < R2N * 3; i += blockDim.x) W[i] = rw3[i];
    if (t < 3) bb[t] = rb3[t];
    __syncthreads();
    int b = blockIdx.x * blockDim.x + t;
    if (b >= BSZ) return;
    const float* h = &g_H2[(size_t)b * R2P];
    float l0 = bb[0], l1 = bb[1], l2 = bb[2];
    #pragma unroll 4
    for (int k = 0; k < R2N; k++) {
        float hv = h[k];
        l0 = fmaf(hv, W[k * 3 + 0], l0);
        l1 = fmaf(hv, W[k * 3 + 1], l1);
        l2 = fmaf(hv, W[k * 3 + 2], l2);
    }
    float s0 = 1.f / (1.f + expf(-l0));
    float s1 = 1.f / (1.f + expf(-l1));
    float s2 = 1.f / (1.f + expf(-l2));
    float e0 = expf(s0), e1 = expf(s1), e2 = expf(s2);
    float inv = 1.f / (e0 + e1 + e2);
    g_w[b * 3 + 0] = e0 * inv;
    g_w[b * 3 + 1] = e1 * inv;
    g_w[b * 3 + 2] = e2 * inv;
}

// Xs[b,:] = fp16([w0*x0[b] | w1*x1[b] | w2*xib[b]])  (vectorized x4)
__global__ void xs_prep_kernel(const float* __restrict__ x0,
                               const float* __restrict__ x1,
                               const float* __restrict__ xib) {
    int i4 = threadIdx.x + blockIdx.x * blockDim.x;
    if (i4 >= BSZ * KTOT / 4) return;
    int idx = i4 * 4;
    int b = idx / KTOT;
    int c = idx - b * KTOT;
    const float* src;
    int off, segi;
    if (c < D0)           { src = x0  + (size_t)b * D0;  off = c;            segi = 0; }
    else if (c < D0 + D1) { src = x1  + (size_t)b * D1;  off = c - D0;       segi = 1; }
    else                  { src = xib + (size_t)b * DIB; off = c - D0 - D1;  segi = 2; }
    float wt = g_w[b * 3 + segi];
    float4 v = *(const float4*)(src + off);
    __half2 o0 = __floats2half2_rn(v.x * wt, v.y * wt);
    __half2 o1 = __floats2half2_rn(v.z * wt, v.w * wt);
    *(__half2*)(g_Xsh + (size_t)i4 * 4)     = o0;
    *(__half2*)(g_Xsh + (size_t)i4 * 4 + 2) = o1;
}

__global__ __launch_bounds__(256)
void l2norm_kernel(float* __restrict__ O) {
    int b = blockIdx.x;
    int t = threadIdx.x;
    float w0 = g_w[b * 3 + 0], w1 = g_w[b * 3 + 1], w2 = g_w[b * 3 + 2];
    float v[6];
    float ss = 0.f;
    #pragma unroll
    for (int i = 0; i < 6; i++) {
        int c = t + i * 256;
        float x = O[(size_t)b * DOUT + c]
                + w0 * g_bavg[c] + w1 * g_bavg[DOUT + c] + w2 * g_bavg[2 * DOUT + c];
        v[i] = x;
        ss += x * x;
    }
    __shared__ float red[256];
    red[t] = ss;
    __syncthreads();
    for (int s = 128; s > 0; s >>= 1) {
        if (t < s) red[t] += red[t + s];
        __syncthreads();
    }
    float inv = 1.0f / fmaxf(sqrtf(red[0]), 1e-12f);
    #pragma unroll
    for (int i = 0; i < 6; i++)
        O[(size_t)b * DOUT + t + i * 256] = v[i] * inv;
}

// ---------------- launch ----------------
#define HGEMM_SMEM (3 * STAGE_BYTES)   // 98304

extern "C" void kernel_launch(void* const* d_in, const int* in_sizes, int n_in,
                              void* d_out, int out_size) {
    const float* x0   = (const float*)d_in[0];
    const float* x1   = (const float*)d_in[1];
    const float* xib  = (const float*)d_in[2];
    const float* pW0  = (const float*)d_in[3];
    const float* pb0  = (const float*)d_in[4];
    const float* pW1  = (const float*)d_in[5];
    const float* pb1  = (const float*)d_in[6];
    const float* pWib = (const float*)d_in[7];
    const float* pbib = (const float*)d_in[8];
    const float* rw1  = (const float*)d_in[9];
    const float* rb1  = (const float*)d_in[10];
    const float* rg1  = (const float*)d_in[11];
    const float* rbt1 = (const float*)d_in[12];
    const float* rw2  = (const float*)d_in[13];
    const float* rb2  = (const float*)d_in[14];
    const float* rg2  = (const float*)d_in[15];
    const float* rbt2 = (const float*)d_in[16];
    const float* rw3  = (const float*)d_in[17];
    const float* rb3  = (const float*)d_in[18];
    float* out = (float*)d_out;

    static float *p_H1, *p_H2, *p_rb2p, *p_s1, *p_q1, *p_s2, *p_q2;
    static __half *p_Wh, *p_rw1Th, *p_rw2Th, *p_x0h, *p_H1h, *p_Xsh;
    static bool s_init = false;
    if (!s_init) {
        cudaGetSymbolAddress((void**)&p_H1,    g_H1);
        cudaGetSymbolAddress((void**)&p_H2,    g_H2);
        cudaGetSymbolAddress((void**)&p_rb2p,  g_rb2p);
        cudaGetSymbolAddress((void**)&p_s1,    g_s1);
        cudaGetSymbolAddress((void**)&p_q1,    g_q1);
        cudaGetSymbolAddress((void**)&p_s2,    g_s2);
        cudaGetSymbolAddress((void**)&p_q2,    g_q2);
        cudaGetSymbolAddress((void**)&p_Wh,    g_Wh);
        cudaGetSymbolAddress((void**)&p_rw1Th, g_rw1Th);
        cudaGetSymbolAddress((void**)&p_rw2Th, g_rw2Th);
        cudaGetSymbolAddress((void**)&p_x0h,   g_x0h);
        cudaGetSymbolAddress((void**)&p_H1h,   g_H1h);
        cudaGetSymbolAddress((void**)&p_Xsh,   g_Xsh);
        cudaFuncSetAttribute(hgemm_kernel, cudaFuncAttributeMaxDynamicSharedMemorySize, HGEMM_SMEM);
        s_init = true;
    }

    // 1. stats zero + rb2 pad
    zero_stats_kernel<<<2, 256>>>(rb2);

    // 2. weight prep (fp16): averaged+transposed experts, transposed router weights, biases, x0h
    wavgT_kernel<<<dim3(KTOT / 32, DOUT / 32), dim3(32, 8)>>>(pW0, pW1, pWib);
    transpose_pad_h_kernel<<<dim3(D0 / 32, R1N / 32), dim3(32, 8)>>>(rw1, p_rw1Th, D0, R1N);
    transpose_pad_h_kernel<<<dim3(R1N / 32, R2P / 32), dim3(32, 8)>>>(rw2, p_rw2Th, R1N, R2N);
    avg_bias_kernel<<<(3 * DOUT + 255) / 256, 256>>>(pb0, pb1, pbib);
    cvt_x0_kernel<<<(BSZ * D0 / 4 + 255) / 256, 256>>>(x0);

    // 3. router layer 1: H1 = x0 @ rw1 + rb1
    hgemm_kernel<<<dim3(R1N / 128, BSZ / 128), 256, HGEMM_SMEM>>>(p_x0h, p_rw1Th, rb1, p_H1, R1N, D0);
    colstats_kernel<<<dim3((R1N + 255) / 256, BSZ / STAT_ROWS), 256>>>(p_H1, R1N, R1N, p_s1, p_q1);
    bn_relu_h_kernel<<<(BSZ * R1N + 255) / 256, 256>>>(rg1, rbt1);

    // 4. router layer 2: H2 = H1h @ rw2p + rb2p
    hgemm_kernel<<<dim3(1, BSZ / 128), 256, HGEMM_SMEM>>>(p_H1h, p_rw2Th, p_rb2p, p_H2, R2P, R1N);
    colstats_kernel<<<dim3(1, BSZ / STAT_ROWS), 256>>>(p_H2, R2P, R2N, p_s2, p_q2);
    bn_tanh_kernel<<<(BSZ * R2P + 255) / 256, 256>>>(rg2, rbt2);

    // 5. router layer 3 + sigmoid + softmax
    router3_kernel<<<BSZ / 256, 256>>>(rw3, rb3);

    // 6. Xs = router-scaled concat (fp16)
    xs_prep_kernel<<<(BSZ * KTOT / 4 + 255) / 256, 256>>>(x0, x1, xib);

    // 7. main GEMM: out = Xs @ Wavg^T
    hgemm_kernel<<<dim3(DOUT / 128, BSZ / 128), 256, HGEMM_SMEM>>>(p_Xsh, p_Wh, nullptr, out, DOUT, KTOT);

    // 8. bias contribution + L2 normalize
    l2norm_kernel<<<BSZ, 256>>>(out);
}

// round 13
// speedup vs baseline: 5.9833x; 1.3961x over previous
#include <cuda_runtime.h>
#include <cuda_fp16.h>
#include <math.h>
#include <stdint.h>

// ---------------- problem dimensions ----------------
#define BSZ   8192
#define D0    1024
#define D1    768
#define DIB   1024
#define KTOT  2816
#define DOUT  1536
#define R1N   512
#define R2N   100
#define R2P   128
#define NEXP  7
#define BN_EPS 1e-5f

// ---------------- scratch ----------------
__device__ __half g_Wh[(size_t)DOUT * KTOT];     // averaged expert weights, transposed [N][K], fp16
__device__ __half g_rw1Th[R1N * D0];             // rw1^T fp16 [512][1024]
__device__ __half g_rw2Th[R2P * R1N];            // rw2^T fp16 [128][512], rows 100..127 zero
__device__ __half g_x0h[(size_t)BSZ * D0];       // x0 fp16
__device__ __half g_H1h[(size_t)BSZ * R1N];      // BN1+relu output fp16
__device__ __half g_Xsh[(size_t)BSZ * KTOT];     // router-scaled concat inputs fp16
__device__ float  g_H1[(size_t)BSZ * R1N];       // router hidden 1 fp32
__device__ float  g_H2[(size_t)BSZ * R2P];       // router hidden 2 fp32
__device__ float  g_bavg[3 * DOUT];
__device__ float  g_rb2p[R2P];
__device__ float  g_s1[R1N], g_q1[R1N];
__device__ float  g_s2[R2P], g_q2[R2P];
__device__ float  g_w[BSZ * 3];

// ---------------- helpers ----------------
__device__ __forceinline__ uint32_t smem_u32(const void* p) {
    uint32_t a;
    asm("{ .reg .u64 t; cvta.to.shared.u64 t, %1; cvt.u32.u64 %0, t; }" : "=r"(a) : "l"(p));
    return a;
}
__device__ __forceinline__ void hmma16(float* c, const uint32_t* a, const uint32_t* b) {
    asm volatile(
        "mma.sync.aligned.m16n8k16.row.col.f32.f16.f16.f32 "
        "{%0,%1,%2,%3},{%4,%5,%6,%7},{%8,%9},{%0,%1,%2,%3};\n"
        : "+f"(c[0]), "+f"(c[1]), "+f"(c[2]), "+f"(c[3])
        : "r"(a[0]), "r"(a[1]), "r"(a[2]), "r"(a[3]), "r"(b[0]), "r"(b[1]));
}
__device__ __forceinline__ void ldsm4(uint32_t* d, uint32_t addr) {
    asm volatile("ldmatrix.sync.aligned.m8n8.x4.shared.b16 {%0,%1,%2,%3}, [%4];"
        : "=r"(d[0]), "=r"(d[1]), "=r"(d[2]), "=r"(d[3]) : "r"(addr));
}

// fragment loader for one k16 step
__device__ __forceinline__ void load_frags(int ks, uint32_t abase, uint32_t bbase,
                                           int a_row0, int a_kch, int b_n0, int b_kch,
                                           uint32_t af[4][4], uint32_t bf[4][2]) {
    #pragma unroll
    for (int mt = 0; mt < 4; mt++) {
        const int row = a_row0 + mt * 16;
        const int kc  = ks * 2 + a_kch;
        ldsm4(af[mt], abase + row * 128 + ((kc ^ (row & 7)) << 4));
    }
    #pragma unroll
    for (int nth = 0; nth < 2; nth++) {
        const int n  = b_n0 + nth * 16;
        const int kc = ks * 2 + b_kch;
        uint32_t t[4];
        ldsm4(t, bbase + n * 128 + ((kc ^ (n & 7)) << 4));
        bf[nth * 2][0]     = t[0]; bf[nth * 2][1]     = t[1];
        bf[nth * 2 + 1][0] = t[2]; bf[nth * 2 + 1][1] = t[3];
    }
}

// ---------------- fp16 tensor-core GEMM (ldmatrix + cp.async, 3-stage, ks-pipelined) ----------------
#define GK 64
#define STAGE_BYTES 32768
__global__ __launch_bounds__(256, 2)
void hgemm_kernel(const __half* __restrict__ A, const __half* __restrict__ BT,
                  const float* __restrict__ bias, float* __restrict__ C,
                  int Ntot, int K) {
    extern __shared__ char smem[];
    const uint32_t sbase = smem_u32(smem);

    const int tid   = threadIdx.x;
    const int warp  = tid >> 5;
    const int lane  = tid & 31;
    const int group = lane >> 2;
    const int tig   = lane & 3;
    const int wm    = (warp & 1) * 64;
    const int wn    = (warp >> 1) * 32;
    const int bm    = blockIdx.y * 128;
    const int bn    = blockIdx.x * 128;
    const int NC    = K / GK;

    float acc[4][4][4];
    #pragma unroll
    for (int i = 0; i < 4; i++)
        #pragma unroll
        for (int j = 0; j < 4; j++)
            #pragma unroll
            for (int l = 0; l < 4; l++) acc[i][j][l] = 0.f;

    auto issue_chunk = [&](int c) {
        const int s = c % 3;
        const uint32_t abase = sbase + s * STAGE_BYTES;
        const uint32_t bbase = abase + 16384;
        const int kb = c * GK;
        #pragma unroll
        for (int it = 0; it < 4; it++) {
            const int idx = tid + it * 256;
            const int r = idx >> 3;
            const int ch = idx & 7;
            const uint32_t so = r * 128 + ((ch ^ (r & 7)) << 4);
            const __half* ga = A  + (size_t)(bm + r) * K + kb + ch * 8;
            const __half* gb = BT + (size_t)(bn + r) * K + kb + ch * 8;
            asm volatile("cp.async.cg.shared.global [%0], [%1], 16;" :: "r"(abase + so), "l"(ga));
            asm volatile("cp.async.cg.shared.global [%0], [%1], 16;" :: "r"(bbase + so), "l"(gb));
        }
        asm volatile("cp.async.commit_group;" ::: "memory");
    };

    issue_chunk(0);
    if (NC > 1) issue_chunk(1);

    const int a_row0 = wm + (lane & 15);
    const int a_kch  = lane >> 4;
    const int b_n0   = wn + ((lane >> 4) << 3) + (lane & 7);
    const int b_kch  = (lane >> 3) & 1;

    uint32_t af[2][4][4], bf[2][4][2];

    for (int c = 0; c < NC; c++) {
        if (c + 1 < NC) asm volatile("cp.async.wait_group 1;" ::: "memory");
        else            asm volatile("cp.async.wait_group 0;" ::: "memory");
        __syncthreads();

        const uint32_t abase = sbase + (c % 3) * STAGE_BYTES;
        const uint32_t bbase = abase + 16384;

        // start fragment loads for ks=0 immediately, then enqueue the next chunk's cp.async
        load_frags(0, abase, bbase, a_row0, a_kch, b_n0, b_kch, af[0], bf[0]);
        if (c + 2 < NC) issue_chunk(c + 2);

        #pragma unroll
        for (int ks = 0; ks < 4; ks++) {
            const int cur = ks & 1;
            if (ks < 3)
                load_frags(ks + 1, abase, bbase, a_row0, a_kch, b_n0, b_kch,
                           af[cur ^ 1], bf[cur ^ 1]);
            #pragma unroll
            for (int mt = 0; mt < 4; mt++)
                #pragma unroll
                for (int nn = 0; nn < 4; nn++)
                    hmma16(acc[mt][nn], af[cur][mt], bf[cur][nn]);
        }
    }

    // epilogue
    #pragma unroll
    for (int mt = 0; mt < 4; mt++) {
        int row = bm + wm + mt * 16 + group;
        #pragma unroll
        for (int nn = 0; nn < 4; nn++) {
            int col = bn + wn + nn * 8 + tig * 2;
            float b0v = 0.f, b1v = 0.f;
            if (bias) { b0v = bias[col]; b1v = bias[col + 1]; }
            float2 v0, v1;
            v0.x = acc[mt][nn][0] + b0v; v0.y = acc[mt][nn][1] + b1v;
            v1.x = acc[mt][nn][2] + b0v; v1.y = acc[mt][nn][3] + b1v;
            *(float2*)&C[(size_t)row * Ntot + col]       = v0;
            *(float2*)&C[(size_t)(row + 8) * Ntot + col] = v1;
        }
    }
}

// ---------------- prep kernels ----------------

__global__ void zero_stats_kernel(const float* __restrict__ rb2) {
    int i = threadIdx.x + blockIdx.x * blockDim.x;
    if (i < R1N) { g_s1[i] = 0.f; g_q1[i] = 0.f; }
    if (i < R2P) { g_s2[i] = 0.f; g_q2[i] = 0.f; g_rb2p[i] = (i < R2N) ? rb2[i] : 0.f; }
}

// averaged + transposed expert weights -> g_Wh[n][k] fp16
__global__ void wavgT_kernel(const float* __restrict__ pW0,
                             const float* __restrict__ pW1,
                             const float* __restrict__ pWib) {
    __shared__ float t[32][33];
    const int k0 = blockIdx.x * 32, n0 = blockIdx.y * 32;
    const int tx = threadIdx.x, ty = threadIdx.y;  // 32x8
    #pragma unroll
    for (int i = 0; i < 4; i++) {
        int k = k0 + ty + i * 8;
        const float* src; int lr, d;
        if (k < D0)           { src = pW0;  lr = k;            d = D0;  }
        else if (k < D0 + D1) { src = pW1;  lr = k - D0;       d = D1;  }
        else                  { src = pWib; lr = k - D0 - D1;  d = DIB; }
        float s = 0.f;
        #pragma unroll
        for (int e = 0; e < NEXP; e++)
            s += src[(size_t)e * d * DOUT + (size_t)lr * DOUT + n0 + tx];
        t[ty + i * 8][tx] = s * (1.0f / NEXP);
    }
    __syncthreads();
    #pragma unroll
    for (int i = 0; i < 4; i++)
        g_Wh[(size_t)(n0 + ty + i * 8) * KTOT + k0 + tx] = __float2half_rn(t[tx][ty + i * 8]);
}

// fp32 [K][N] -> fp16 transposed [NP][K], zero-padded rows n>=N
__global__ void transpose_pad_h_kernel(const float* __restrict__ in, __half* __restrict__ out,
                                       int K, int N) {
    __shared__ float t[32][33];
    const int k0 = blockIdx.x * 32, n0 = blockIdx.y * 32;
    const int tx = threadIdx.x, ty = threadIdx.y;
    #pragma unroll
    for (int i = 0; i < 4; i++) {
        int n = n0 + tx;
        t[ty + i * 8][tx] = (n < N) ? in[(size_t)(k0 + ty + i * 8) * N + n] : 0.f;
    }
    __syncthreads();
    #pragma unroll
    for (int i = 0; i < 4; i++)
        out[(size_t)(n0 + ty + i * 8) * K + k0 + tx] = __float2half_rn(t[tx][ty + i * 8]);
}

__global__ void avg_bias_kernel(const float* __restrict__ pb0,
                                const float* __restrict__ pb1,
                                const float* __restrict__ pbib) {
    int idx = threadIdx.x + blockIdx.x * blockDim.x;
    if (idx >= 3 * DOUT) return;
    int seg = idx / DOUT;
    int c = idx - seg * DOUT;
    const float* src = (seg == 0) ? pb0 : (seg == 1) ? pb1 : pbib;
    float s = 0.f;
    #pragma unroll
    for (int e = 0; e < NEXP; e++) s += src[e * DOUT + c];
    g_bavg[idx] = s * (1.0f / NEXP);
}

// x0 fp32 -> fp16 (vectorized x4)
__global__ void cvt_x0_kernel(const float* __restrict__ x0) {
    int i4 = threadIdx.x + blockIdx.x * blockDim.x;
    if (i4 >= BSZ * D0 / 4) return;
    float4 v = ((const float4*)x0)[i4];
    __half2 o0 = __floats2half2_rn(v.x, v.y);
    __half2 o1 = __floats2half2_rn(v.z, v.w);
    *(__half2*)(g_x0h + (size_t)i4 * 4)     = o0;
    *(__half2*)(g_x0h + (size_t)i4 * 4 + 2) = o1;
}

#define STAT_ROWS 256
__global__ void colstats_kernel(const float* __restrict__ H, int Nstride, int N,
                                float* __restrict__ s, float* __restrict__ q) {
    int c = threadIdx.x + blockIdx.x * blockDim.x;
    if (c >= N) return;
    int r0 = blockIdx.y * STAT_ROWS;
    float sum = 0.f, sq = 0.f;
    for (int r = r0; r < r0 + STAT_ROWS; r++) {
        float v = H[(size_t)r * Nstride + c];
        sum += v; sq += v * v;
    }
    atomicAdd(&s[c], sum);
    atomicAdd(&q[c], sq);
}

// BN1 + relu: fp32 H1 -> fp16 H1h
__global__ void bn_relu_h_kernel(const float* __restrict__ g, const float* __restrict__ bt) {
    int idx = threadIdx.x + blockIdx.x * blockDim.x;
    if (idx >= BSZ * R1N) return;
    int c = idx % R1N;
    float mean = g_s1[c] * (1.0f / BSZ);
    float var  = g_q1[c] * (1.0f / BSZ) - mean * mean;
    float rstd = rsqrtf(var + BN_EPS);
    float v = g[c] * (g_H1[idx] - mean) * rstd + bt[c];
    g_H1h[idx] = __float2half_rn(fmaxf(v, 0.f));
}

// BN2 + tanh in-place on fp32 H2 (cols >= R2N skipped)
__global__ void bn_tanh_kernel(const float* __restrict__ g, const float* __restrict__ bt) {
    int idx = threadIdx.x + blockIdx.x * blockDim.x;
    if (idx >= BSZ * R2P) return;
    int c = idx % R2P;
    if (c >= R2N) return;
    float mean = g_s2[c] * (1.0f / BSZ);
    float var  = g_q2[c] * (1.0f / BSZ) - mean * mean;
    float rstd = rsqrtf(var + BN_EPS);
    float v = g[c] * (g_H2[idx] - mean) * rstd + bt[c];
    g_H2[idx] = tanhf(v);
}

__global__ void router3_kernel(const float* __restrict__ rw3,
                               const float* __restrict__ rb3) {
    __shared__ float W[R2N * 3];
    __shared__ float bb[3];
    int t = threadIdx.x;
    for (int i = t; i < R2N * 3; i += blockDim.x) W[i] = rw3[i];
    if (t < 3) bb[t] = rb3[t];
    __syncthreads();
    int b = blockIdx.x * blockDim.x + t;
    if (b >= BSZ) return;
    const float* h = &g_H2[(size_t)b * R2P];
    float l0 = bb[0], l1 = bb[1], l2 = bb[2];
    #pragma unroll 4
    for (int k = 0; k < R2N; k++) {
        float hv = h[k];
        l0 = fmaf(hv, W[k * 3 + 0], l0);
        l1 = fmaf(hv, W[k * 3 + 1], l1);
        l2 = fmaf(hv, W[k * 3 + 2], l2);
    }
    float s0 = 1.f / (1.f + expf(-l0));
    float s1 = 1.f / (1.f + expf(-l1));
    float s2 = 1.f / (1.f + expf(-l2));
    float e0 = expf(s0), e1 = expf(s1), e2 = expf(s2);
    float inv = 1.f / (e0 + e1 + e2);
    g_w[b * 3 + 0] = e0 * inv;
    g_w[b * 3 + 1] = e1 * inv;
    g_w[b * 3 + 2] = e2 * inv;
}

// Xs[b,:] = fp16([w0*x0[b] | w1*x1[b] | w2*xib[b]])  (vectorized x4)
__global__ void xs_prep_kernel(const float* __restrict__ x0,
                               const float* __restrict__ x1,
                               const float* __restrict__ xib) {
    int i4 = threadIdx.x + blockIdx.x * blockDim.x;
    if (i4 >= BSZ * KTOT / 4) return;
    int idx = i4 * 4;
    int b = idx / KTOT;
    int c = idx - b * KTOT;
    const float* src;
    int off, segi;
    if (c < D0)           { src = x0  + (size_t)b * D0;  off = c;            segi = 0; }
    else if (c < D0 + D1) { src = x1  + (size_t)b * D1;  off = c - D0;       segi = 1; }
    else                  { src = xib + (size_t)b * DIB; off = c - D0 - D1;  segi = 2; }
    float wt = g_w[b * 3 + segi];
    float4 v = *(const float4*)(src + off);
    __half2 o0 = __floats2half2_rn(v.x * wt, v.y * wt);
    __half2 o1 = __floats2half2_rn(v.z * wt, v.w * wt);
    *(__half2*)(g_Xsh + (size_t)i4 * 4)     = o0;
    *(__half2*)(g_Xsh + (size_t)i4 * 4 + 2) = o1;
}

__global__ __launch_bounds__(256)
void l2norm_kernel(float* __restrict__ O) {
    int b = blockIdx.x;
    int t = threadIdx.x;
    float w0 = g_w[b * 3 + 0], w1 = g_w[b * 3 + 1], w2 = g_w[b * 3 + 2];
    float v[6];
    float ss = 0.f;
    #pragma unroll
    for (int i = 0; i < 6; i++) {
        int c = t + i * 256;
        float x = O[(size_t)b * DOUT + c]
                + w0 * g_bavg[c] + w1 * g_bavg[DOUT + c] + w2 * g_bavg[2 * DOUT + c];
        v[i] = x;
        ss += x * x;
    }
    __shared__ float red[256];
    red[t] = ss;
    __syncthreads();
    for (int s = 128; s > 0; s >>= 1) {
        if (t < s) red[t] += red[t + s];
        __syncthreads();
    }
    float inv = 1.0f / fmaxf(sqrtf(red[0]), 1e-12f);
    #pragma unroll
    for (int i = 0; i < 6; i++)
        O[(size_t)b * DOUT + t + i * 256] = v[i] * inv;
}

// ---------------- launch ----------------
#define HGEMM_SMEM (3 * STAGE_BYTES)   // 98304

extern "C" void kernel_launch(void* const* d_in, const int* in_sizes, int n_in,
                              void* d_out, int out_size) {
    const float* x0   = (const float*)d_in[0];
    const float* x1   = (const float*)d_in[1];
    const float* xib  = (const float*)d_in[2];
    const float* pW0  = (const float*)d_in[3];
    const float* pb0  = (const float*)d_in[4];
    const float* pW1  = (const float*)d_in[5];
    const float* pb1  = (const float*)d_in[6];
    const float* pWib = (const float*)d_in[7];
    const float* pbib = (const float*)d_in[8];
    const float* rw1  = (const float*)d_in[9];
    const float* rb1  = (const float*)d_in[10];
    const float* rg1  = (const float*)d_in[11];
    const float* rbt1 = (const float*)d_in[12];
    const float* rw2  = (const float*)d_in[13];
    const float* rb2  = (const float*)d_in[14];
    const float* rg2  = (const float*)d_in[15];
    const float* rbt2 = (const float*)d_in[16];
    const float* rw3  = (const float*)d_in[17];
    const float* rb3  = (const float*)d_in[18];
    float* out = (float*)d_out;

    static float *p_H1, *p_H2, *p_rb2p, *p_s1, *p_q1, *p_s2, *p_q2;
    static __half *p_Wh, *p_rw1Th, *p_rw2Th, *p_x0h, *p_H1h, *p_Xsh;
    static bool s_init = false;
    if (!s_init) {
        cudaGetSymbolAddress((void**)&p_H1,    g_H1);
        cudaGetSymbolAddress((void**)&p_H2,    g_H2);
        cudaGetSymbolAddress((void**)&p_rb2p,  g_rb2p);
        cudaGetSymbolAddress((void**)&p_s1,    g_s1);
        cudaGetSymbolAddress((void**)&p_q1,    g_q1);
        cudaGetSymbolAddress((void**)&p_s2,    g_s2);
        cudaGetSymbolAddress((void**)&p_q2,    g_q2);
        cudaGetSymbolAddress((void**)&p_Wh,    g_Wh);
        cudaGetSymbolAddress((void**)&p_rw1Th, g_rw1Th);
        cudaGetSymbolAddress((void**)&p_rw2Th, g_rw2Th);
        cudaGetSymbolAddress((void**)&p_x0h,   g_x0h);
        cudaGetSymbolAddress((void**)&p_H1h,   g_H1h);
        cudaGetSymbolAddress((void**)&p_Xsh,   g_Xsh);
        cudaFuncSetAttribute(hgemm_kernel, cudaFuncAttributeMaxDynamicSharedMemorySize, HGEMM_SMEM);
        s_init = true;
    }

    // 1. stats zero + rb2 pad
    zero_stats_kernel<<<2, 256>>>(rb2);

    // 2. weight prep (fp16)
    wavgT_kernel<<<dim3(KTOT / 32, DOUT / 32), dim3(32, 8)>>>(pW0, pW1, pWib);
    transpose_pad_h_kernel<<<dim3(D0 / 32, R1N / 32), dim3(32, 8)>>>(rw1, p_rw1Th, D0, R1N);
    transpose_pad_h_kernel<<<dim3(R1N / 32, R2P / 32), dim3(32, 8)>>>(rw2, p_rw2Th, R1N, R2N);
    avg_bias_kernel<<<(3 * DOUT + 255) / 256, 256>>>(pb0, pb1, pbib);
    cvt_x0_kernel<<<(BSZ * D0 / 4 + 255) / 256, 256>>>(x0);

    // 3. router layer 1: H1 = x0 @ rw1 + rb1
    hgemm_kernel<<<dim3(R1N / 128, BSZ / 128), 256, HGEMM_SMEM>>>(p_x0h, p_rw1Th, rb1, p_H1, R1N, D0);
    colstats_kernel<<<dim3((R1N + 255) / 256, BSZ / STAT_ROWS), 256>>>(p_H1, R1N, R1N, p_s1, p_q1);
    bn_relu_h_kernel<<<(BSZ * R1N + 255) / 256, 256>>>(rg1, rbt1);

    // 4. router layer 2: H2 = H1h @ rw2p + rb2p
    hgemm_kernel<<<dim3(1, BSZ / 128), 256, HGEMM_SMEM>>>(p_H1h, p_rw2Th, p_rb2p, p_H2, R2P, R1N);
    colstats_kernel<<<dim3(1, BSZ / STAT_ROWS), 256>>>(p_H2, R2P, R2N, p_s2, p_q2);
    bn_tanh_kernel<<<(BSZ * R2P + 255) / 256, 256>>>(rg2, rbt2);

    // 5. router layer 3 + sigmoid + softmax
    router3_kernel<<<BSZ / 256, 256>>>(rw3, rb3);

    // 6. Xs = router-scaled concat (fp16)
    xs_prep_kernel<<<(BSZ * KTOT / 4 + 255) / 256, 256>>>(x0, x1, xib);

    // 7. main GEMM: out = Xs @ Wavg^T
    hgemm_kernel<<<dim3(DOUT / 128, BSZ / 128), 256, HGEMM_SMEM>>>(p_Xsh, p_Wh, nullptr, out, DOUT, KTOT);

    // 8. bias contribution + L2 normalize
    l2norm_kernel<<<BSZ, 256>>>(out);
}

// round 16
// speedup vs baseline: 6.0077x; 1.0041x over previous
#include <cuda_runtime.h>
#include <cuda_fp16.h>
#include <math.h>
#include <stdint.h>

// ---------------- problem dimensions ----------------
#define BSZ   8192
#define D0    1024
#define D1    768
#define DIB   1024
#define KTOT  2816
#define DOUT  1536
#define R1N   512
#define R2N   100
#define R2P   128
#define NEXP  7
#define BN_EPS 1e-5f

// ---------------- scratch ----------------
__device__ __half g_Wh[(size_t)DOUT * KTOT];
__device__ __half g_rw1Th[R1N * D0];
__device__ __half g_rw2Th[R2P * R1N];
__device__ __half g_x0h[(size_t)BSZ * D0];
__device__ __half g_H1h[(size_t)BSZ * R1N];
__device__ __half g_Xsh[(size_t)BSZ * KTOT];
__device__ float  g_H1[(size_t)BSZ * R1N];
__device__ float  g_H2[(size_t)BSZ * R2P];
__device__ float  g_bavg[3 * DOUT];
__device__ float  g_rb2p[R2P];
__device__ float  g_s1[R1N], g_q1[R1N];
__device__ float  g_s2[R2P], g_q2[R2P];
__device__ float  g_w[BSZ * 3];

// ---------------- helpers ----------------
__device__ __forceinline__ uint32_t smem_u32(const void* p) {
    uint32_t a;
    asm("{ .reg .u64 t; cvta.to.shared.u64 t, %1; cvt.u32.u64 %0, t; }" : "=r"(a) : "l"(p));
    return a;
}
__device__ __forceinline__ void hmma16(float* c, const uint32_t* a, const uint32_t* b) {
    asm volatile(
        "mma.sync.aligned.m16n8k16.row.col.f32.f16.f16.f32 "
        "{%0,%1,%2,%3},{%4,%5,%6,%7},{%8,%9},{%0,%1,%2,%3};\n"
        : "+f"(c[0]), "+f"(c[1]), "+f"(c[2]), "+f"(c[3])
        : "r"(a[0]), "r"(a[1]), "r"(a[2]), "r"(a[3]), "r"(b[0]), "r"(b[1]));
}
__device__ __forceinline__ void ldsm4(uint32_t* d, uint32_t addr) {
    asm volatile("ldmatrix.sync.aligned.m8n8.x4.shared.b16 {%0,%1,%2,%3}, [%4];"
        : "=r"(d[0]), "=r"(d[1]), "=r"(d[2]), "=r"(d[3]) : "r"(addr));
}

__device__ __forceinline__ void load_frags(int ks, uint32_t abase, uint32_t bbase,
                                           int a_row0, int a_kch, int b_n0, int b_kch,
                                           uint32_t af[4][4], uint32_t bf[4][2]) {
    #pragma unroll
    for (int mt = 0; mt < 4; mt++) {
        const int row = a_row0 + mt * 16;
        const int kc  = ks * 2 + a_kch;
        ldsm4(af[mt], abase + row * 128 + ((kc ^ (row & 7)) << 4));
    }
    #pragma unroll
    for (int nth = 0; nth < 2; nth++) {
        const int n  = b_n0 + nth * 16;
        const int kc = ks * 2 + b_kch;
        uint32_t t[4];
        ldsm4(t, bbase + n * 128 + ((kc ^ (n & 7)) << 4));
        bf[nth * 2][0]     = t[0]; bf[nth * 2][1]     = t[1];
        bf[nth * 2 + 1][0] = t[2]; bf[nth * 2 + 1][1] = t[3];
    }
}

// ---------------- fp16 tensor-core GEMM (ldmatrix + cp.async, 3-stage, ks-pipelined) -------
// STATS=1: additionally atomicAdd per-column sums/sumsq of (acc+bias) into sp/qp.
#define GK 64
#define STAGE_BYTES 32768
template<int STATS>
__global__ __launch_bounds__(256, 2)
void hgemm_kernel(const __half* __restrict__ A, const __half* __restrict__ BT,
                  const float* __restrict__ bias, float* __restrict__ C,
                  int Ntot, int K, float* __restrict__ sp, float* __restrict__ qp) {
    extern __shared__ char smem[];
    const uint32_t sbase = smem_u32(smem);

    const int tid   = threadIdx.x;
    const int warp  = tid >> 5;
    const int lane  = tid & 31;
    const int group = lane >> 2;
    const int tig   = lane & 3;
    const int wm    = (warp & 1) * 64;
    const int wn    = (warp >> 1) * 32;
    const int bm    = blockIdx.y * 128;
    const int bn    = blockIdx.x * 128;
    const int NC    = K / GK;

    float acc[4][4][4];
    #pragma unroll
    for (int i = 0; i < 4; i++)
        #pragma unroll
        for (int j = 0; j < 4; j++)
            #pragma unroll
            for (int l = 0; l < 4; l++) acc[i][j][l] = 0.f;

    auto issue_chunk = [&](int c) {
        const int s = c % 3;
        const uint32_t abase = sbase + s * STAGE_BYTES;
        const uint32_t bbase = abase + 16384;
        const int kb = c * GK;
        #pragma unroll
        for (int it = 0; it < 4; it++) {
            const int idx = tid + it * 256;
            const int r = idx >> 3;
            const int ch = idx & 7;
            const uint32_t so = r * 128 + ((ch ^ (r & 7)) << 4);
            const __half* ga = A  + (size_t)(bm + r) * K + kb + ch * 8;
            const __half* gb = BT + (size_t)(bn + r) * K + kb + ch * 8;
            asm volatile("cp.async.cg.shared.global [%0], [%1], 16;" :: "r"(abase + so), "l"(ga));
            asm volatile("cp.async.cg.shared.global [%0], [%1], 16;" :: "r"(bbase + so), "l"(gb));
        }
        asm volatile("cp.async.commit_group;" ::: "memory");
    };

    issue_chunk(0);
    if (NC > 1) issue_chunk(1);

    const int a_row0 = wm + (lane & 15);
    const int a_kch  = lane >> 4;
    const int b_n0   = wn + ((lane >> 4) << 3) + (lane & 7);
    const int b_kch  = (lane >> 3) & 1;

    uint32_t af[2][4][4], bf[2][4][2];

    for (int c = 0; c < NC; c++) {
        if (c + 1 < NC) asm volatile("cp.async.wait_group 1;" ::: "memory");
        else            asm volatile("cp.async.wait_group 0;" ::: "memory");
        __syncthreads();

        const uint32_t abase = sbase + (c % 3) * STAGE_BYTES;
        const uint32_t bbase = abase + 16384;

        load_frags(0, abase, bbase, a_row0, a_kch, b_n0, b_kch, af[0], bf[0]);
        if (c + 2 < NC) issue_chunk(c + 2);

        #pragma unroll
        for (int ks = 0; ks < 4; ks++) {
            const int cur = ks & 1;
            if (ks < 3)
                load_frags(ks + 1, abase, bbase, a_row0, a_kch, b_n0, b_kch,
                           af[cur ^ 1], bf[cur ^ 1]);
            #pragma unroll
            for (int mt = 0; mt < 4; mt++)
                #pragma unroll
                for (int nn = 0; nn < 4; nn++)
                    hmma16(acc[mt][nn], af[cur][mt], bf[cur][nn]);
        }
    }

    // epilogue (optionally accumulating batch stats)
    #pragma unroll
    for (int nn = 0; nn < 4; nn++) {
        const int col = bn + wn + nn * 8 + tig * 2;
        float b0v = 0.f, b1v = 0.f;
        if (bias) { b0v = bias[col]; b1v = bias[col + 1]; }
        float s0 = 0.f, q0 = 0.f, s1 = 0.f, q1 = 0.f;
        #pragma unroll
        for (int mt = 0; mt < 4; mt++) {
            const int row = bm + wm + mt * 16 + group;
            float v00 = acc[mt][nn][0] + b0v, v01 = acc[mt][nn][1] + b1v;
            float v10 = acc[mt][nn][2] + b0v, v11 = acc[mt][nn][3] + b1v;
            float2 w0; w0.x = v00; w0.y = v01;
            float2 w1; w1.x = v10; w1.y = v11;
            *(float2*)&C[(size_t)row * Ntot + col]       = w0;
            *(float2*)&C[(size_t)(row + 8) * Ntot + col] = w1;
            if (STATS) {
                s0 += v00 + v10; q0 += v00 * v00 + v10 * v10;
                s1 += v01 + v11; q1 += v01 * v01 + v11 * v11;
            }
        }
        if (STATS) {
            atomicAdd(&sp[col],     s0);
            atomicAdd(&qp[col],     q0);
            atomicAdd(&sp[col + 1], s1);
            atomicAdd(&qp[col + 1], q1);
        }
    }
}

// ---------------- fused prep mega-kernel ----------------
// Block ranges:
//   [0, 4224)           wavgT: averaged+transposed expert weights -> g_Wh
//   [4224, 4736)        transpose rw1 -> g_rw1Th
//   [4736, 4800)        transpose rw2 (pad to 128) -> g_rw2Th
//   [4800, 4818)        avg_bias -> g_bavg
//   [4818, 4819)        zero stats + rb2 pad
//   [4819, 13011)       cvt x0 -> g_x0h
#define PB_W   4224
#define PB_T1  (PB_W + 512)
#define PB_T2  (PB_T1 + 64)
#define PB_B   (PB_T2 + 18)
#define PB_Z   (PB_B + 1)
#define PB_X0  (PB_Z + 8192)

__device__ __forceinline__ void transpose_body(float (*t)[33], const float* __restrict__ in,
                                               __half* __restrict__ out, int K, int N,
                                               int k0, int n0, int tx, int ty) {
    #pragma unroll
    for (int i = 0; i < 4; i++) {
        int n = n0 + tx;
        t[ty + i * 8][tx] = (n < N) ? in[(size_t)(k0 + ty + i * 8) * N + n] : 0.f;
    }
    __syncthreads();
    #pragma unroll
    for (int i = 0; i < 4; i++)
        out[(size_t)(n0 + ty + i * 8) * K + k0 + tx] = __float2half_rn(t[tx][ty + i * 8]);
}

__global__ __launch_bounds__(256)
void prep_kernel(const float* __restrict__ pW0, const float* __restrict__ pW1,
                 const float* __restrict__ pWib,
                 const float* __restrict__ rw1, const float* __restrict__ rw2,
                 const float* __restrict__ rb2,
                 const float* __restrict__ pb0, const float* __restrict__ pb1,
                 const float* __restrict__ pbib,
                 const float* __restrict__ x0) {
    __shared__ float t[32][33];
    const int b = blockIdx.x;
    const int tid = threadIdx.x;
    const int tx = tid & 31, ty = tid >> 5;

    if (b < PB_W) {
        const int k0 = (b % (KTOT / 32)) * 32;
        const int n0 = (b / (KTOT / 32)) * 32;
        #pragma unroll
        for (int i = 0; i < 4; i++) {
            int k = k0 + ty + i * 8;
            const float* src; int lr, d;
            if (k < D0)           { src = pW0;  lr = k;            d = D0;  }
            else if (k < D0 + D1) { src = pW1;  lr = k - D0;       d = D1;  }
            else                  { src = pWib; lr = k - D0 - D1;  d = DIB; }
            float s = 0.f;
            #pragma unroll
            for (int e = 0; e < NEXP; e++)
                s += src[(size_t)e * d * DOUT + (size_t)lr * DOUT + n0 + tx];
            t[ty + i * 8][tx] = s * (1.0f / NEXP);
        }
        __syncthreads();
        #pragma unroll
        for (int i = 0; i < 4; i++)
            g_Wh[(size_t)(n0 + ty + i * 8) * KTOT + k0 + tx] = __float2half_rn(t[tx][ty + i * 8]);
    } else if (b < PB_T1) {
        const int idx = b - PB_W;
        transpose_body(t, rw1, g_rw1Th, D0, R1N, (idx % (D0 / 32)) * 32, (idx / (D0 / 32)) * 32, tx, ty);
    } else if (b < PB_T2) {
        const int idx = b - PB_T1;
        transpose_body(t, rw2, g_rw2Th, R1N, R2N, (idx % (R1N / 32)) * 32, (idx / (R1N / 32)) * 32, tx, ty);
    } else if (b < PB_B) {
        const int idx = (b - PB_T2) * 256 + tid;
        if (idx < 3 * DOUT) {
            int seg = idx / DOUT;
            int c = idx - seg * DOUT;
            const float* src = (seg == 0) ? pb0 : (seg == 1) ? pb1 : pbib;
            float s = 0.f;
            #pragma unroll
            for (int e = 0; e < NEXP; e++) s += src[e * DOUT + c];
            g_bavg[idx] = s * (1.0f / NEXP);
        }
    } else if (b < PB_Z) {
        for (int i = tid; i < R1N; i += 256) { g_s1[i] = 0.f; g_q1[i] = 0.f; }
        if (tid < R2P) { g_s2[tid] = 0.f; g_q2[tid] = 0.f; g_rb2p[tid] = (tid < R2N) ? rb2[tid] : 0.f; }
    } else {
        const int i4 = (b - PB_Z) * 256 + tid;
        float4 v = ((const float4*)x0)[i4];
        __half2 o0 = __floats2half2_rn(v.x, v.y);
        __half2 o1 = __floats2half2_rn(v.z, v.w);
        *(__half2*)(g_x0h + (size_t)i4 * 4)     = o0;
        *(__half2*)(g_x0h + (size_t)i4 * 4 + 2) = o1;
    }
}

// ---------------- remaining elementwise kernels ----------------

// BN1 + relu: fp32 H1 -> fp16 H1h
__global__ void bn_relu_h_kernel(const float* __restrict__ g, const float* __restrict__ bt) {
    int idx = threadIdx.x + blockIdx.x * blockDim.x;
    if (idx >= BSZ * R1N) return;
    int c = idx % R1N;
    float mean = g_s1[c] * (1.0f / BSZ);
    float var  = g_q1[c] * (1.0f / BSZ) - mean * mean;
    float rstd = rsqrtf(var + BN_EPS);
    float v = g[c] * (g_H1[idx] - mean) * rstd + bt[c];
    g_H1h[idx] = __float2half_rn(fmaxf(v, 0.f));
}

// router layer 3 with fused BN2+tanh: reads raw H2, applies per-col affine + tanh inline
__global__ void router3_kernel(const float* __restrict__ rw3, const float* __restrict__ rb3,
                               const float* __restrict__ rg2, const float* __restrict__ rbt2) {
    __shared__ float W[R2N * 3];
    __shared__ float bb[3];
    __shared__ float sc[R2N], sh[R2N];
    int t = threadIdx.x;
    for (int i = t; i < R2N * 3; i += blockDim.x) W[i] = rw3[i];
    if (t < 3) bb[t] = rb3[t];
    if (t < R2N) {
        float mean = g_s2[t] * (1.0f / BSZ);
        float var  = g_q2[t] * (1.0f / BSZ) - mean * mean;
        float rstd = rsqrtf(var + BN_EPS);
        float scale = rg2[t] * rstd;
        sc[t] = scale;
        sh[t] = rbt2[t] - mean * scale;
    }
    __syncthreads();
    int b = blockIdx.x * blockDim.x + t;
    if (b >= BSZ) return;
    const float* h = &g_H2[(size_t)b * R2P];
    float l0 = bb[0], l1 = bb[1], l2 = bb[2];
    #pragma unroll 4
    for (int k = 0; k < R2N; k++) {
        float hv = tanhf(fmaf(h[k], sc[k], sh[k]));
        l0 = fmaf(hv, W[k * 3 + 0], l0);
        l1 = fmaf(hv, W[k * 3 + 1], l1);
        l2 = fmaf(hv, W[k * 3 + 2], l2);
    }
    float s0 = 1.f / (1.f + expf(-l0));
    float s1 = 1.f / (1.f + expf(-l1));
    float s2 = 1.f / (1.f + expf(-l2));
    float e0 = expf(s0), e1 = expf(s1), e2 = expf(s2);
    float inv = 1.f / (e0 + e1 + e2);
    g_w[b * 3 + 0] = e0 * inv;
    g_w[b * 3 + 1] = e1 * inv;
    g_w[b * 3 + 2] = e2 * inv;
}

// Xs[b,:] = fp16([w0*x0[b] | w1*x1[b] | w2*xib[b]])
__global__ void xs_prep_kernel(const float* __restrict__ x0,
                               const float* __restrict__ x1,
                               const float* __restrict__ xib) {
    int i4 = threadIdx.x + blockIdx.x * blockDim.x;
    if (i4 >= BSZ * KTOT / 4) return;
    int idx = i4 * 4;
    int b = idx / KTOT;
    int c = idx - b * KTOT;
    const float* src;
    int off, segi;
    if (c < D0)           { src = x0  + (size_t)b * D0;  off = c;            segi = 0; }
    else if (c < D0 + D1) { src = x1  + (size_t)b * D1;  off = c - D0;       segi = 1; }
    else                  { src = xib + (size_t)b * DIB; off = c - D0 - D1;  segi = 2; }
    float wt = g_w[b * 3 + segi];
    float4 v = *(const float4*)(src + off);
    __half2 o0 = __floats2half2_rn(v.x * wt, v.y * wt);
    __half2 o1 = __floats2half2_rn(v.z * wt, v.w * wt);
    *(__half2*)(g_Xsh + (size_t)i4 * 4)     = o0;
    *(__half2*)(g_Xsh + (size_t)i4 * 4 + 2) = o1;
}

__global__ __launch_bounds__(256)
void l2norm_kernel(float* __restrict__ O) {
    int b = blockIdx.x;
    int t = threadIdx.x;
    float w0 = g_w[b * 3 + 0], w1 = g_w[b * 3 + 1], w2 = g_w[b * 3 + 2];
    float v[6];
    float ss = 0.f;
    #pragma unroll
    for (int i = 0; i < 6; i++) {
        int c = t + i * 256;
        float x = O[(size_t)b * DOUT + c]
                + w0 * g_bavg[c] + w1 * g_bavg[DOUT + c] + w2 * g_bavg[2 * DOUT + c];
        v[i] = x;
        ss += x * x;
    }
    __shared__ float red[256];
    red[t] = ss;
    __syncthreads();
    for (int s = 128; s > 0; s >>= 1) {
        if (t < s) red[t] += red[t + s];
        __syncthreads();
    }
    float inv = 1.0f / fmaxf(sqrtf(red[0]), 1e-12f);
    #pragma unroll
    for (int i = 0; i < 6; i++)
        O[(size_t)b * DOUT + t + i * 256] = v[i] * inv;
}

// ---------------- launch ----------------
#define HGEMM_SMEM (3 * STAGE_BYTES)   // 98304

extern "C" void kernel_launch(void* const* d_in, const int* in_sizes, int n_in,
                              void* d_out, int out_size) {
    const float* x0   = (const float*)d_in[0];
    const float* x1   = (const float*)d_in[1];
    const float* xib  = (const float*)d_in[2];
    const float* pW0  = (const float*)d_in[3];
    const float* pb0  = (const float*)d_in[4];
    const float* pW1  = (const float*)d_in[5];
    const float* pb1  = (const float*)d_in[6];
    const float* pWib = (const float*)d_in[7];
    const float* pbib = (const float*)d_in[8];
    const float* rw1  = (const float*)d_in[9];
    const float* rb1  = (const float*)d_in[10];
    const float* rg1  = (const float*)d_in[11];
    const float* rbt1 = (const float*)d_in[12];
    const float* rw2  = (const float*)d_in[13];
    const float* rb2  = (const float*)d_in[14];
    const float* rg2  = (const float*)d_in[15];
    const float* rbt2 = (const float*)d_in[16];
    const float* rw3  = (const float*)d_in[17];
    const float* rb3  = (const float*)d_in[18];
    float* out = (float*)d_out;

    static float *p_H1, *p_H2, *p_rb2p, *p_s1, *p_q1, *p_s2, *p_q2;
    static __half *p_Wh, *p_rw1Th, *p_rw2Th, *p_x0h, *p_H1h, *p_Xsh;
    static bool s_init = false;
    if (!s_init) {
        cudaGetSymbolAddress((void**)&p_H1,    g_H1);
        cudaGetSymbolAddress((void**)&p_H2,    g_H2);
        cudaGetSymbolAddress((void**)&p_rb2p,  g_rb2p);
        cudaGetSymbolAddress((void**)&p_s1,    g_s1);
        cudaGetSymbolAddress((void**)&p_q1,    g_q1);
        cudaGetSymbolAddress((void**)&p_s2,    g_s2);
        cudaGetSymbolAddress((void**)&p_q2,    g_q2);
        cudaGetSymbolAddress((void**)&p_Wh,    g_Wh);
        cudaGetSymbolAddress((void**)&p_rw1Th, g_rw1Th);
        cudaGetSymbolAddress((void**)&p_rw2Th, g_rw2Th);
        cudaGetSymbolAddress((void**)&p_x0h,   g_x0h);
        cudaGetSymbolAddress((void**)&p_H1h,   g_H1h);
        cudaGetSymbolAddress((void**)&p_Xsh,   g_Xsh);
        cudaFuncSetAttribute(hgemm_kernel<0>, cudaFuncAttributeMaxDynamicSharedMemorySize, HGEMM_SMEM);
        cudaFuncSetAttribute(hgemm_kernel<1>, cudaFuncAttributeMaxDynamicSharedMemorySize, HGEMM_SMEM);
        s_init = true;
    }

    // 1. fused prep: Wavg^T, rw1^T, rw2^T, bias avg, x0->fp16, stat zero, rb2 pad
    prep_kernel<<<PB_X0, 256>>>(pW0, pW1, pWib, rw1, rw2, rb2, pb0, pb1, pbib, x0);

    // 2. router layer 1 (+fused batch stats)
    hgemm_kernel<1><<<dim3(R1N / 128, BSZ / 128), 256, HGEMM_SMEM>>>(
        p_x0h, p_rw1Th, rb1, p_H1, R1N, D0, p_s1, p_q1);
    bn_relu_h_kernel<<<(BSZ * R1N + 255) / 256, 256>>>(rg1, rbt1);

    // 3. router layer 2 (+fused batch stats)
    hgemm_kernel<1><<<dim3(1, BSZ / 128), 256, HGEMM_SMEM>>>(
        p_H1h, p_rw2Th, p_rb2p, p_H2, R2P, R1N, p_s2, p_q2);

    // 4. router layer 3 (fused BN2 + tanh) + sigmoid + softmax
    router3_kernel<<<BSZ / 256, 256>>>(rw3, rb3, rg2, rbt2);

    // 5. Xs = router-scaled concat (fp16)
    xs_prep_kernel<<<(BSZ * KTOT / 4 + 255) / 256, 256>>>(x0, x1, xib);

    // 6. main GEMM: out = Xs @ Wavg^T
    hgemm_kernel<0><<<dim3(DOUT / 128, BSZ / 128), 256, HGEMM_SMEM>>>(
        p_Xsh, p_Wh, nullptr, out, DOUT, KTOT, nullptr, nullptr);

    // 7. bias contribution + L2 normalize
    l2norm_kernel<<<BSZ, 256>>>(out);
}